// round 2
// baseline (speedup 1.0000x reference)
#include <cuda_runtime.h>

#define NB 8
#define NT 1024
#define ND 512
#define NH 8
#define NDH 64
#define NSPOS 2047
#define ATT_SCALE 0.125f

// Scratch (device globals; no allocations allowed)
__device__ float g_q[NB*NH*NT*NDH];
__device__ float g_k[NB*NH*NT*NDH];
__device__ float g_v[NB*NH*NT*NDH];
__device__ float g_p[NH*NSPOS*NDH];
__device__ float g_ao[NB*NT*ND];

// ---------------------------------------------------------------------------
// SGEMM: C[M,512] = A[M,512] @ W[512,512] (+bias). 128x128 tile, BK=16,
// 256 threads, 8x8 register fragments. Epilogue layout by MODE:
//   MODE 0: plain row-major C[m*512+n]
//   MODE 1: scatter to [b][h][t][d]  (m=b*1024+t, n=h*64+d)
//   MODE 2: scatter to [h][m][d]     (pos projection, m in [0,2047))
// ---------------------------------------------------------------------------
template<int MODE>
__global__ __launch_bounds__(256)
void sgemm_k(const float* __restrict__ A, const float* __restrict__ W,
             const float* __restrict__ bias, float* __restrict__ C, int M)
{
    __shared__ float As[16][132];
    __shared__ float Bs[16][132];
    const int tid = threadIdx.x;
    const int tx = tid & 15;
    const int ty = tid >> 4;
    const int row0 = blockIdx.x << 7;
    const int col0 = blockIdx.y << 7;

    float acc[8][8];
#pragma unroll
    for (int i = 0; i < 8; i++)
#pragma unroll
        for (int j = 0; j < 8; j++) acc[i][j] = 0.f;

    const int arow = tid >> 2;
    const int acol = (tid & 3) << 2;
    const int brow = tid >> 5;
    const int bcol = (tid & 31) << 2;

    for (int k0 = 0; k0 < 512; k0 += 16) {
#pragma unroll
        for (int ph = 0; ph < 2; ph++) {
            int r = arow + (ph << 6);
            int gr = row0 + r;
            float4 va = (gr < M) ? *(const float4*)(A + (size_t)gr * 512 + k0 + acol)
                                 : make_float4(0.f, 0.f, 0.f, 0.f);
            As[acol + 0][r] = va.x;
            As[acol + 1][r] = va.y;
            As[acol + 2][r] = va.z;
            As[acol + 3][r] = va.w;
        }
#pragma unroll
        for (int ph = 0; ph < 2; ph++) {
            int r = brow + (ph << 3);
            *(float4*)&Bs[r][bcol] = *(const float4*)(W + (size_t)(k0 + r) * 512 + col0 + bcol);
        }
        __syncthreads();
#pragma unroll
        for (int kk = 0; kk < 16; kk++) {
            float af[8], bf[8];
            *(float4*)&af[0] = *(const float4*)&As[kk][ty << 3];
            *(float4*)&af[4] = *(const float4*)&As[kk][(ty << 3) + 4];
            *(float4*)&bf[0] = *(const float4*)&Bs[kk][tx << 3];
            *(float4*)&bf[4] = *(const float4*)&Bs[kk][(tx << 3) + 4];
#pragma unroll
            for (int i = 0; i < 8; i++)
#pragma unroll
                for (int j = 0; j < 8; j++)
                    acc[i][j] += af[i] * bf[j];
        }
        __syncthreads();
    }

#pragma unroll
    for (int i = 0; i < 8; i++) {
        int m = row0 + (ty << 3) + i;
        if (m >= M) continue;
#pragma unroll
        for (int j4 = 0; j4 < 2; j4++) {
            int n = col0 + (tx << 3) + (j4 << 2);
            float4 bb = bias ? *(const float4*)(bias + n) : make_float4(0.f,0.f,0.f,0.f);
            float4 o;
            o.x = acc[i][j4 * 4 + 0] + bb.x;
            o.y = acc[i][j4 * 4 + 1] + bb.y;
            o.z = acc[i][j4 * 4 + 2] + bb.z;
            o.w = acc[i][j4 * 4 + 3] + bb.w;
            if (MODE == 0) {
                *(float4*)(C + (size_t)m * 512 + n) = o;
            } else if (MODE == 1) {
                int b = m >> 10, t = m & 1023;
                int h = n >> 6,  d = n & 63;
                *(float4*)(C + ((size_t)((b << 3) + h) * NT + t) * NDH + d) = o;
            } else {
                int h = n >> 6, d = n & 63;
                *(float4*)(C + ((size_t)h * NSPOS + m) * NDH + d) = o;
            }
        }
    }
}

// ---------------------------------------------------------------------------
// Flash-style attention with relative position band gather.
// Grid: B*H*(T/64) blocks, 256 threads. Each block: 64 queries, loops over
// 16 key tiles of 64. pos score: S_pos[t,s] = q_v[t] . p[1023 + s - t]
// (derived closed form of the reference's _relative_shift).
// Fragment mapping (strided): r = ty + 16*i, c = tx + 16*j  -> the p band
// index (c - r + 63) depends only on (j - i): 7 distinct smem rows/thread/d.
// ---------------------------------------------------------------------------
__global__ __launch_bounds__(256)
void attn_k(const float* __restrict__ q, const float* __restrict__ k,
            const float* __restrict__ v, const float* __restrict__ p,
            const float* __restrict__ pbu, const float* __restrict__ pbv,
            float* __restrict__ out)
{
    extern __shared__ float smbuf[];
    float* squ = smbuf;            // 64*65
    float* sqv = squ + 64 * 65;    // 64*65
    float* sk  = sqv + 64 * 65;    // 64*65
    float* sv  = sk  + 64 * 65;    // 64*65
    float* sp  = sv  + 64 * 65;    // 127*65
    float* sP  = sp  + 127 * 65;   // 64*65

    const int tid = threadIdx.x;
    const int tx = tid & 15;
    const int ty = tid >> 4;
    const int bx = blockIdx.x;
    const int t0 = (bx & 15) << 6;
    const int bh = bx >> 4;
    const int h  = bh & 7;
    const int b  = bh >> 3;

    const float* qb = q + ((size_t)bh * NT + t0) * NDH;
    const float* kb = k + (size_t)bh * NT * NDH;
    const float* vb = v + (size_t)bh * NT * NDH;
    const float* pb = p + (size_t)h * NSPOS * NDH;

    // load q tile once; build q+u and q+v copies
#pragma unroll
    for (int pp = 0; pp < 4; pp++) {
        int e = tid + (pp << 8);
        int r = e >> 4;
        int d4 = (e & 15) << 2;
        float4 qq = *(const float4*)(qb + r * NDH + d4);
        float4 uu = *(const float4*)(pbu + h * NDH + d4);
        float4 vv = *(const float4*)(pbv + h * NDH + d4);
        squ[r*65 + d4 + 0] = qq.x + uu.x;
        squ[r*65 + d4 + 1] = qq.y + uu.y;
        squ[r*65 + d4 + 2] = qq.z + uu.z;
        squ[r*65 + d4 + 3] = qq.w + uu.w;
        sqv[r*65 + d4 + 0] = qq.x + vv.x;
        sqv[r*65 + d4 + 1] = qq.y + vv.y;
        sqv[r*65 + d4 + 2] = qq.z + vv.z;
        sqv[r*65 + d4 + 3] = qq.w + vv.w;
    }

    float m_i[4], l_i[4], O[4][4];
#pragma unroll
    for (int i = 0; i < 4; i++) {
        m_i[i] = -3.0e38f;
        l_i[i] = 0.f;
#pragma unroll
        for (int j = 0; j < 4; j++) O[i][j] = 0.f;
    }

    const int e0 = tx - ty + 63;   // band row for (j - i) == 0

    for (int s0 = 0; s0 < NT; s0 += 64) {
        __syncthreads();   // previous AV done before tiles are overwritten
        // K, V tiles
#pragma unroll
        for (int pp = 0; pp < 4; pp++) {
            int e = tid + (pp << 8);
            int r = e >> 4;
            int d4 = (e & 15) << 2;
            float4 kk = *(const float4*)(kb + (size_t)(s0 + r) * NDH + d4);
            sk[r*65+d4+0] = kk.x; sk[r*65+d4+1] = kk.y;
            sk[r*65+d4+2] = kk.z; sk[r*65+d4+3] = kk.w;
            float4 vv = *(const float4*)(vb + (size_t)(s0 + r) * NDH + d4);
            sv[r*65+d4+0] = vv.x; sv[r*65+d4+1] = vv.y;
            sv[r*65+d4+2] = vv.z; sv[r*65+d4+3] = vv.w;
        }
        // p band: rows pbase..pbase+126 (out-of-range rows are never used; clamp)
        int pbase = 960 + s0 - t0;
#pragma unroll
        for (int pp = 0; pp < 8; pp++) {
            int e = tid + (pp << 8);
            if (e < 2032) {
                int jj = e >> 4;
                int d4 = (e & 15) << 2;
                int jidx = pbase + jj;
                jidx = jidx < 0 ? 0 : (jidx > 2046 ? 2046 : jidx);
                float4 pv4 = *(const float4*)(pb + (size_t)jidx * NDH + d4);
                sp[jj*65+d4+0] = pv4.x; sp[jj*65+d4+1] = pv4.y;
                sp[jj*65+d4+2] = pv4.z; sp[jj*65+d4+3] = pv4.w;
            }
        }
        __syncthreads();

        // scores: S = (q+u).k + (q+v).p_band
        float S[4][4];
#pragma unroll
        for (int i = 0; i < 4; i++)
#pragma unroll
            for (int j = 0; j < 4; j++) S[i][j] = 0.f;

#pragma unroll 4
        for (int d = 0; d < 64; d++) {
            float au[4], av[4], kc[4], pv[7];
#pragma unroll
            for (int i = 0; i < 4; i++) {
                au[i] = squ[(ty + (i << 4)) * 65 + d];
                av[i] = sqv[(ty + (i << 4)) * 65 + d];
            }
#pragma unroll
            for (int j = 0; j < 4; j++) kc[j] = sk[(tx + (j << 4)) * 65 + d];
#pragma unroll
            for (int dl = 0; dl < 7; dl++)
                pv[dl] = sp[(e0 + (dl << 4) - 48) * 65 + d];
#pragma unroll
            for (int i = 0; i < 4; i++)
#pragma unroll
                for (int j = 0; j < 4; j++)
                    S[i][j] += au[i] * kc[j] + av[i] * pv[j - i + 3];
        }

        // online softmax (rows owned by 16-lane groups; butterfly shfl reduce)
#pragma unroll
        for (int i = 0; i < 4; i++) {
            float mt = -3.0e38f;
#pragma unroll
            for (int j = 0; j < 4; j++) {
                S[i][j] *= ATT_SCALE;
                mt = fmaxf(mt, S[i][j]);
            }
#pragma unroll
            for (int off = 8; off >= 1; off >>= 1)
                mt = fmaxf(mt, __shfl_xor_sync(0xffffffffu, mt, off));
            float mn = fmaxf(m_i[i], mt);
            float alpha = __expf(m_i[i] - mn);
            m_i[i] = mn;
            float rs = 0.f;
#pragma unroll
            for (int j = 0; j < 4; j++) {
                float ev = __expf(S[i][j] - mn);
                S[i][j] = ev;
                rs += ev;
            }
#pragma unroll
            for (int off = 8; off >= 1; off >>= 1)
                rs += __shfl_xor_sync(0xffffffffu, rs, off);
            l_i[i] = l_i[i] * alpha + rs;
#pragma unroll
            for (int j = 0; j < 4; j++) O[i][j] *= alpha;
#pragma unroll
            for (int j = 0; j < 4; j++)
                sP[(ty + (i << 4)) * 65 + tx + (j << 4)] = S[i][j];
        }
        __syncthreads();

        // O += P @ V
#pragma unroll 4
        for (int c = 0; c < 64; c++) {
            float pr[4], vf[4];
#pragma unroll
            for (int i = 0; i < 4; i++) pr[i] = sP[(ty + (i << 4)) * 65 + c];
#pragma unroll
            for (int j = 0; j < 4; j++) vf[j] = sv[c * 65 + tx + (j << 4)];
#pragma unroll
            for (int i = 0; i < 4; i++)
#pragma unroll
                for (int j = 0; j < 4; j++)
                    O[i][j] += pr[i] * vf[j];
        }
    }

    // normalize and write to [b][t][h*64+d] so final projection is plain GEMM
#pragma unroll
    for (int i = 0; i < 4; i++) {
        float inv = 1.f / l_i[i];
        int r = ty + (i << 4);
#pragma unroll
        for (int j = 0; j < 4; j++) {
            int dc = tx + (j << 4);
            out[((size_t)b * NT + t0 + r) * ND + h * NDH + dc] = O[i][j] * inv;
        }
    }
}

// ---------------------------------------------------------------------------
extern "C" void kernel_launch(void* const* d_in, const int* in_sizes, int n_in,
                              void* d_out, int out_size)
{
    const float* x    = (const float*)d_in[0];
    const float* pe   = (const float*)d_in[1];
    const float* Wq   = (const float*)d_in[2];
    const float* bq   = (const float*)d_in[3];
    const float* Wk   = (const float*)d_in[4];
    const float* bk   = (const float*)d_in[5];
    const float* Wv   = (const float*)d_in[6];
    const float* bv   = (const float*)d_in[7];
    const float* Wpos = (const float*)d_in[8];
    const float* pbu  = (const float*)d_in[9];
    const float* pbv  = (const float*)d_in[10];
    const float* Wo   = (const float*)d_in[11];
    const float* bo   = (const float*)d_in[12];
    float* out = (float*)d_out;

    float *qp, *kp, *vp, *pp, *aop;
    cudaGetSymbolAddress((void**)&qp,  g_q);
    cudaGetSymbolAddress((void**)&kp,  g_k);
    cudaGetSymbolAddress((void**)&vp,  g_v);
    cudaGetSymbolAddress((void**)&pp,  g_p);
    cudaGetSymbolAddress((void**)&aop, g_ao);

    const int smem = (64 * 65 * 5 + 127 * 65) * (int)sizeof(float);  // 116220 B
    cudaFuncSetAttribute(attn_k, cudaFuncAttributeMaxDynamicSharedMemorySize, smem);

    dim3 blk(256);
    sgemm_k<1><<<dim3(64, 4), blk>>>(x,  Wq,   bq,      qp,  NB * NT);
    sgemm_k<1><<<dim3(64, 4), blk>>>(x,  Wk,   bk,      kp,  NB * NT);
    sgemm_k<1><<<dim3(64, 4), blk>>>(x,  Wv,   bv,      vp,  NB * NT);
    sgemm_k<2><<<dim3(16, 4), blk>>>(pe, Wpos, nullptr, pp,  NSPOS);
    attn_k<<<NB * NH * (NT / 64), blk, smem>>>(qp, kp, vp, pp, pbu, pbv, aop);
    sgemm_k<0><<<dim3(64, 4), blk>>>(aop, Wo,  bo,      out, NB * NT);
}

// round 7
// speedup vs baseline: 1.2098x; 1.2098x over previous
#include <cuda_runtime.h>

#define NB 8
#define NT 1024
#define ND 512
#define NH 8
#define NDH 64
#define NSPOS 2047
#define ATT_SCALE 0.125f

typedef unsigned long long ull;

// Scratch (device globals; no allocations allowed)
__device__ float g_q[NB*NH*NT*NDH];
__device__ float g_k[NB*NH*NT*NDH];
__device__ float g_v[NB*NH*NT*NDH];
__device__ float g_p[NH*NSPOS*NDH];
__device__ float g_ao[NB*NT*ND];
__device__ float g_uk[NB*NH*NT];
__device__ float g_vp[NH*NSPOS];

__device__ __forceinline__ void ffma2(ull &d, ull a, ull b) {
    asm("fma.rn.f32x2 %0, %1, %2, %0;" : "+l"(d) : "l"(a), "l"(b));
}
__device__ __forceinline__ void fmul2(ull &d, ull a) {
    asm("mul.rn.f32x2 %0, %0, %1;" : "+l"(d) : "l"(a));
}
__device__ __forceinline__ ull fdup(float x) {
    ull r; asm("mov.b64 %0, {%1, %1};" : "=l"(r) : "f"(x)); return r;
}
__device__ __forceinline__ float2 unpk(ull v) {
    float2 f; asm("mov.b64 {%0, %1}, %2;" : "=f"(f.x), "=f"(f.y) : "l"(v)); return f;
}

// ---------------------------------------------------------------------------
// SGEMM with packed f32x2 FMA: C[M,512] = A[M,512] @ W[512,512] (+bias).
// 128x128 tile, BK=16, 256 threads, 8x8 fragments held as 8x4 f32x2 pairs.
//   MODE 0: row-major C;  MODE 1: scatter [b][h][t][d];  MODE 2: [h][m][d]
// ---------------------------------------------------------------------------
template<int MODE>
__global__ __launch_bounds__(256)
void sgemm_k(const float* __restrict__ A, const float* __restrict__ W,
             const float* __restrict__ bias, float* __restrict__ C, int M)
{
    __shared__ float As[16][132];
    __shared__ float Bs[16][132];
    const int tid = threadIdx.x;
    const int tx = tid & 15;
    const int ty = tid >> 4;
    const int row0 = blockIdx.x << 7;
    const int col0 = blockIdx.y << 7;

    ull acc2[8][4];
#pragma unroll
    for (int i = 0; i < 8; i++)
#pragma unroll
        for (int j = 0; j < 4; j++) acc2[i][j] = 0ull;

    const int arow = tid >> 2;
    const int acol = (tid & 3) << 2;
    const int brow = tid >> 5;
    const int bcol = (tid & 31) << 2;

    for (int k0 = 0; k0 < 512; k0 += 16) {
#pragma unroll
        for (int ph = 0; ph < 2; ph++) {
            int r = arow + (ph << 6);
            int gr = row0 + r;
            float4 va = (gr < M) ? *(const float4*)(A + (size_t)gr * 512 + k0 + acol)
                                 : make_float4(0.f, 0.f, 0.f, 0.f);
            As[acol + 0][r] = va.x;
            As[acol + 1][r] = va.y;
            As[acol + 2][r] = va.z;
            As[acol + 3][r] = va.w;
        }
#pragma unroll
        for (int ph = 0; ph < 2; ph++) {
            int r = brow + (ph << 3);
            *(float4*)&Bs[r][bcol] = *(const float4*)(W + (size_t)(k0 + r) * 512 + col0 + bcol);
        }
        __syncthreads();
#pragma unroll
        for (int kk = 0; kk < 16; kk++) {
            float af[8];
            *(float4*)&af[0] = *(const float4*)&As[kk][ty << 3];
            *(float4*)&af[4] = *(const float4*)&As[kk][(ty << 3) + 4];
            const ull* bp = (const ull*)&Bs[kk][tx << 3];
            ull b0 = bp[0], b1 = bp[1], b2 = bp[2], b3 = bp[3];
#pragma unroll
            for (int i = 0; i < 8; i++) {
                ull ad = fdup(af[i]);
                ffma2(acc2[i][0], ad, b0);
                ffma2(acc2[i][1], ad, b1);
                ffma2(acc2[i][2], ad, b2);
                ffma2(acc2[i][3], ad, b3);
            }
        }
        __syncthreads();
    }

#pragma unroll
    for (int i = 0; i < 8; i++) {
        int m = row0 + (ty << 3) + i;
        if (m >= M) continue;
#pragma unroll
        for (int j4 = 0; j4 < 2; j4++) {
            int n = col0 + (tx << 3) + (j4 << 2);
            float4 bb = bias ? *(const float4*)(bias + n) : make_float4(0.f,0.f,0.f,0.f);
            float2 pa = unpk(acc2[i][j4 * 2 + 0]);
            float2 pb = unpk(acc2[i][j4 * 2 + 1]);
            float4 o;
            o.x = pa.x + bb.x;
            o.y = pa.y + bb.y;
            o.z = pb.x + bb.z;
            o.w = pb.y + bb.w;
            if (MODE == 0) {
                *(float4*)(C + (size_t)m * 512 + n) = o;
            } else if (MODE == 1) {
                int b = m >> 10, t = m & 1023;
                int h = n >> 6,  d = n & 63;
                *(float4*)(C + ((size_t)((b << 3) + h) * NT + t) * NDH + d) = o;
            } else {
                int h = n >> 6, d = n & 63;
                *(float4*)(C + ((size_t)h * NSPOS + m) * NDH + d) = o;
            }
        }
    }
}

// ---------------------------------------------------------------------------
// Precompute uk[b,h,s] = pos_bias_u[h] . k[b,h,s]  and
//            vp[h,idx] = pos_bias_v[h] . p[h,idx].  One warp per row.
// ---------------------------------------------------------------------------
#define NUKROWS (NB*NH*NT)
#define NVPROWS (NH*NSPOS)
__global__ __launch_bounds__(256)
void biasdot_k(const float* __restrict__ k, const float* __restrict__ p,
               const float* __restrict__ pbu, const float* __restrict__ pbv,
               float* __restrict__ uk, float* __restrict__ vp)
{
    int w = (blockIdx.x * 256 + threadIdx.x) >> 5;
    int lane = threadIdx.x & 31;
    if (w < NUKROWS) {
        int h = (w >> 10) & 7;
        float2 a = *(const float2*)(k + (size_t)w * NDH + lane * 2);
        float2 u = *(const float2*)(pbu + h * NDH + lane * 2);
        float s = a.x * u.x + a.y * u.y;
#pragma unroll
        for (int off = 16; off >= 1; off >>= 1)
            s += __shfl_xor_sync(0xffffffffu, s, off);
        if (lane == 0) uk[w] = s;
    } else if (w < NUKROWS + NVPROWS) {
        int r = w - NUKROWS;
        float2 a = *(const float2*)(p + (size_t)r * NDH + lane * 2);
        int h = r / NSPOS;
        float2 u = *(const float2*)(pbv + h * NDH + lane * 2);
        float s = a.x * u.x + a.y * u.y;
#pragma unroll
        for (int off = 16; off >= 1; off >>= 1)
            s += __shfl_xor_sync(0xffffffffu, s, off);
        if (lane == 0) vp[r] = s;
    }
}

// ---------------------------------------------------------------------------
// Flash attention, 128 queries x 64 keys per tile, 256 threads,
// 8x4 fragments, f32x2 packed along the d (contraction) axis.
// score S[t,s] = q.k[s] + q.p[1023+s-t] + uk[s] + vp[1023+s-t], then *SCALE.
// Thread map: tx = tid>>4 (row group, r = tx+16i), ty = tid&15 (col, c = ty+16j).
// p band rows share across fragment: band offset depends only on (j-i): 11 rows.
// ---------------------------------------------------------------------------
#define SQ_OFF 0
#define SK_OFF 8448            // 128*66
#define SV_OFF 12672           // + 64*66
#define SP_OFF 17024           // + 64*68
#define SPR_OFF 29630          // + 191*66
#define SUK_OFF 46270          // + 128*130
#define SVP_OFF 46334          // + 64
#define SM_FLOATS 46532        // + 191 (+ round)

__global__ __launch_bounds__(256)
void attn_k(const float* __restrict__ q, const float* __restrict__ k,
            const float* __restrict__ v, const float* __restrict__ p,
            const float* __restrict__ uk, const float* __restrict__ vp,
            float* __restrict__ out)
{
    extern __shared__ float sm[];
    float* sq  = sm + SQ_OFF;    // [128][66]
    float* sk_ = sm + SK_OFF;    // [64][66]
    float* sv_ = sm + SV_OFF;    // [64][68]
    float* sp_ = sm + SP_OFF;    // [191][66]
    float* sPs = sm + SPR_OFF;   // [128][130]
    float* suk = sm + SUK_OFF;   // [64]
    float* svp = sm + SVP_OFF;   // [191]

    const int tid = threadIdx.x;
    const int tx = tid >> 4;     // 0..15 (row group)
    const int ty = tid & 15;     // 0..15 (col group)
    const int bx = blockIdx.x;
    const int t0 = (bx & 7) << 7;
    const int bh = bx >> 3;
    const int h  = bh & 7;
    const int b  = bh >> 3;

    const float* qb = q + ((size_t)bh * NT + t0) * NDH;
    const float* kb = k + (size_t)bh * NT * NDH;
    const float* vb = v + (size_t)bh * NT * NDH;
    const float* pb = p + (size_t)h * NSPOS * NDH;

    // load q tile: 128 x 64
#pragma unroll
    for (int pp = 0; pp < 8; pp++) {
        int e = tid + (pp << 8);
        int r = e >> 4;
        int d4 = (e & 15) << 2;
        float4 t = *(const float4*)(qb + r * NDH + d4);
        sq[r*66 + d4 + 0] = t.x;
        sq[r*66 + d4 + 1] = t.y;
        sq[r*66 + d4 + 2] = t.z;
        sq[r*66 + d4 + 3] = t.w;
    }

    ull O2[8][2];
    float m_i[8], l_i[8];
#pragma unroll
    for (int i = 0; i < 8; i++) {
        m_i[i] = -3.0e38f;
        l_i[i] = 0.f;
        O2[i][0] = 0ull;
        O2[i][1] = 0ull;
    }

    const int pbrow = ty - tx + 15;   // band base row (dl = 0)

    for (int s0 = 0; s0 < NT; s0 += 64) {
        __syncthreads();   // prior AV / q store complete before overwrite
        // K, V tiles (64 x 64 each)
#pragma unroll
        for (int pp = 0; pp < 4; pp++) {
            int e = tid + (pp << 8);
            int r = e >> 4;
            int d4 = (e & 15) << 2;
            float4 kk = *(const float4*)(kb + (size_t)(s0 + r) * NDH + d4);
            sk_[r*66+d4+0] = kk.x; sk_[r*66+d4+1] = kk.y;
            sk_[r*66+d4+2] = kk.z; sk_[r*66+d4+3] = kk.w;
            float4 vv = *(const float4*)(vb + (size_t)(s0 + r) * NDH + d4);
            sv_[r*68+d4+0] = vv.x; sv_[r*68+d4+1] = vv.y;
            sv_[r*68+d4+2] = vv.z; sv_[r*68+d4+3] = vv.w;
        }
        // p band: 191 rows, global index pbase + jj, always in [0,2046]
        const int pbase = 896 + s0 - t0;
#pragma unroll
        for (int pp = 0; pp < 12; pp++) {
            int e = tid + (pp << 8);
            if (e < 191 * 16) {
                int r = e >> 4;
                int d4 = (e & 15) << 2;
                float4 pv4 = *(const float4*)(pb + (size_t)(pbase + r) * NDH + d4);
                sp_[r*66+d4+0] = pv4.x; sp_[r*66+d4+1] = pv4.y;
                sp_[r*66+d4+2] = pv4.z; sp_[r*66+d4+3] = pv4.w;
            }
        }
        if (tid < 64)  suk[tid] = uk[bh * NT + s0 + tid];
        if (tid < 191) svp[tid] = vp[h * NSPOS + pbase + tid];
        __syncthreads();

        // ---- scores (f32x2 packed along d) ----
        ull S2[8][4];
#pragma unroll
        for (int i = 0; i < 8; i++)
#pragma unroll
            for (int j = 0; j < 4; j++) S2[i][j] = 0ull;

#pragma unroll 4
        for (int d2 = 0; d2 < 64; d2 += 2) {
            ull qp[8], kp[4], pv[11];
#pragma unroll
            for (int i = 0; i < 8; i++)
                qp[i] = *(const ull*)(sq + (tx + (i << 4)) * 66 + d2);
#pragma unroll
            for (int j = 0; j < 4; j++)
                kp[j] = *(const ull*)(sk_ + (ty + (j << 4)) * 66 + d2);
#pragma unroll
            for (int dl = 0; dl < 11; dl++)
                pv[dl] = *(const ull*)(sp_ + (pbrow + (dl << 4)) * 66 + d2);
#pragma unroll
            for (int i = 0; i < 8; i++)
#pragma unroll
                for (int j = 0; j < 4; j++) {
                    ffma2(S2[i][j], qp[i], kp[j]);
                    ffma2(S2[i][j], qp[i], pv[j - i + 7]);
                }
        }

        // ---- online softmax (rows owned by 16-lane groups) ----
#pragma unroll
        for (int i = 0; i < 8; i++) {
            float s[4];
            float mt = -3.0e38f;
#pragma unroll
            for (int j = 0; j < 4; j++) {
                float2 f = unpk(S2[i][j]);
                s[j] = (f.x + f.y + suk[ty + (j << 4)]
                        + svp[pbrow + ((j - i + 7) << 4)]) * ATT_SCALE;
                mt = fmaxf(mt, s[j]);
            }
#pragma unroll
            for (int off = 8; off >= 1; off >>= 1)
                mt = fmaxf(mt, __shfl_xor_sync(0xffffffffu, mt, off));
            float mn = fmaxf(m_i[i], mt);
            float alpha = __expf(m_i[i] - mn);
            m_i[i] = mn;
            float rs = 0.f;
#pragma unroll
            for (int j = 0; j < 4; j++) {
                float ev = __expf(s[j] - mn);
                s[j] = ev;
                rs += ev;
            }
#pragma unroll
            for (int off = 8; off >= 1; off >>= 1)
                rs += __shfl_xor_sync(0xffffffffu, rs, off);
            l_i[i] = l_i[i] * alpha + rs;
            ull ad = fdup(alpha);
            fmul2(O2[i][0], ad);
            fmul2(O2[i][1], ad);
#pragma unroll
            for (int j = 0; j < 4; j++)
                sPs[(tx + (i << 4)) * 130 + ty + (j << 4)] = s[j];
        }
        __syncthreads();

        // ---- O += P @ V (f32x2 packed along d) ----
#pragma unroll 4
        for (int c = 0; c < 64; c++) {
            const ull* vrow = (const ull*)(sv_ + c * 68 + (ty << 2));
            ull v0 = vrow[0], v1 = vrow[1];
#pragma unroll
            for (int i = 0; i < 8; i++) {
                ull pd = fdup(sPs[(tx + (i << 4)) * 130 + c]);
                ffma2(O2[i][0], pd, v0);
                ffma2(O2[i][1], pd, v1);
            }
        }
    }

    // normalize, write to [b][t][h*64+d]
#pragma unroll
    for (int i = 0; i < 8; i++) {
        float inv = 1.f / l_i[i];
        float2 a = unpk(O2[i][0]);
        float2 c2 = unpk(O2[i][1]);
        float4 o;
        o.x = a.x * inv;  o.y = a.y * inv;
        o.z = c2.x * inv; o.w = c2.y * inv;
        int r = tx + (i << 4);
        *(float4*)(out + ((size_t)b * NT + t0 + r) * ND + h * NDH + (ty << 2)) = o;
    }
}

// ---------------------------------------------------------------------------
extern "C" void kernel_launch(void* const* d_in, const int* in_sizes, int n_in,
                              void* d_out, int out_size)
{
    const float* x    = (const float*)d_in[0];
    const float* pe   = (const float*)d_in[1];
    const float* Wq   = (const float*)d_in[2];
    const float* bq   = (const float*)d_in[3];
    const float* Wk   = (const float*)d_in[4];
    const float* bk   = (const float*)d_in[5];
    const float* Wv   = (const float*)d_in[6];
    const float* bv   = (const float*)d_in[7];
    const float* Wpos = (const float*)d_in[8];
    const float* pbu  = (const float*)d_in[9];
    const float* pbv  = (const float*)d_in[10];
    const float* Wo   = (const float*)d_in[11];
    const float* bo   = (const float*)d_in[12];
    float* out = (float*)d_out;

    float *qp, *kp, *vp_, *pp, *aop, *ukp, *vpp;
    cudaGetSymbolAddress((void**)&qp,  g_q);
    cudaGetSymbolAddress((void**)&kp,  g_k);
    cudaGetSymbolAddress((void**)&vp_, g_v);
    cudaGetSymbolAddress((void**)&pp,  g_p);
    cudaGetSymbolAddress((void**)&aop, g_ao);
    cudaGetSymbolAddress((void**)&ukp, g_uk);
    cudaGetSymbolAddress((void**)&vpp, g_vp);

    const int smem = SM_FLOATS * (int)sizeof(float);  // 186128 B
    cudaFuncSetAttribute(attn_k, cudaFuncAttributeMaxDynamicSharedMemorySize, smem);

    dim3 blk(256);
    sgemm_k<1><<<dim3(64, 4), blk>>>(x,  Wq,   bq,      qp,  NB * NT);
    sgemm_k<1><<<dim3(64, 4), blk>>>(x,  Wk,   bk,      kp,  NB * NT);
    sgemm_k<1><<<dim3(64, 4), blk>>>(x,  Wv,   bv,      vp_, NB * NT);
    sgemm_k<2><<<dim3(16, 4), blk>>>(pe, Wpos, nullptr, pp,  NSPOS);
    biasdot_k<<<(NUKROWS + NVPROWS + 7) / 8, blk>>>(kp, pp, pbu, pbv, ukp, vpp);
    attn_k<<<NB * NH * (NT / 128), blk, smem>>>(qp, kp, vp_, pp, ukp, vpp, aop);
    sgemm_k<0><<<dim3(64, 4), blk>>>(aop, Wo,  bo,      out, NB * NT);
}

// round 8
// speedup vs baseline: 1.2267x; 1.0140x over previous
#include <cuda_runtime.h>

#define NB 8
#define NT 1024
#define ND 512
#define NH 8
#define NDH 64
#define NSPOS 2047
#define ATT_SCALE 0.125f

typedef unsigned long long ull;

// Scratch (device globals; no allocations allowed)
__device__ float g_q[NB*NH*NT*NDH];
__device__ float g_k[NB*NH*NT*NDH];
__device__ float g_v[NB*NH*NT*NDH];
__device__ float g_p[NH*NSPOS*NDH];
__device__ float g_ao[NB*NT*ND];
__device__ float g_uk[NB*NH*NT];
__device__ float g_vp[NH*NSPOS];

__device__ __forceinline__ void ffma2(ull &d, ull a, ull b) {
    asm("fma.rn.f32x2 %0, %1, %2, %0;" : "+l"(d) : "l"(a), "l"(b));
}
__device__ __forceinline__ void fmul2(ull &d, ull a) {
    asm("mul.rn.f32x2 %0, %0, %1;" : "+l"(d) : "l"(a));
}
__device__ __forceinline__ ull fdup(float x) {
    ull r; asm("mov.b64 %0, {%1, %1};" : "=l"(r) : "f"(x)); return r;
}
__device__ __forceinline__ float2 unpk(ull v) {
    float2 f; asm("mov.b64 {%0, %1}, %2;" : "=f"(f.x), "=f"(f.y) : "l"(v)); return f;
}

// ---------------------------------------------------------------------------
// Double-buffered SGEMM body (shared by both kernels below).
// C[M,512] = A[M,512] @ W[512,512] (+bias). 128x128 tile, BK=16, 256 thr,
// 8x8 fragments as 8x4 f32x2 pairs. One __syncthreads per K-slice.
// ---------------------------------------------------------------------------
struct SmemGemm {
    float As[2][16][132];
    float Bs[2][16][132];
};

template<int MODE>
__device__ __forceinline__
void sgemm_body(const float* __restrict__ A, const float* __restrict__ W,
                const float* __restrict__ bias, float* __restrict__ C,
                int M, int row0, int col0, SmemGemm* s)
{
    const int tid = threadIdx.x;
    const int tx = tid & 15;
    const int ty = tid >> 4;

    ull acc2[8][4];
#pragma unroll
    for (int i = 0; i < 8; i++)
#pragma unroll
        for (int j = 0; j < 4; j++) acc2[i][j] = 0ull;

    const int arow = tid >> 2;
    const int acol = (tid & 3) << 2;
    const int brow = tid >> 5;
    const int bcol = (tid & 31) << 2;
    const int gr0 = row0 + arow;
    const int gr1 = row0 + arow + 64;

    // preload slice 0 into buffer 0
    {
        float4 va0 = (gr0 < M) ? *(const float4*)(A + (size_t)gr0 * 512 + acol)
                               : make_float4(0.f,0.f,0.f,0.f);
        float4 va1 = (gr1 < M) ? *(const float4*)(A + (size_t)gr1 * 512 + acol)
                               : make_float4(0.f,0.f,0.f,0.f);
        s->As[0][acol+0][arow] = va0.x; s->As[0][acol+1][arow] = va0.y;
        s->As[0][acol+2][arow] = va0.z; s->As[0][acol+3][arow] = va0.w;
        s->As[0][acol+0][arow+64] = va1.x; s->As[0][acol+1][arow+64] = va1.y;
        s->As[0][acol+2][arow+64] = va1.z; s->As[0][acol+3][arow+64] = va1.w;
        *(float4*)&s->Bs[0][brow    ][bcol] = *(const float4*)(W + (size_t)(brow    ) * 512 + col0 + bcol);
        *(float4*)&s->Bs[0][brow + 8][bcol] = *(const float4*)(W + (size_t)(brow + 8) * 512 + col0 + bcol);
    }
    __syncthreads();

    int cur = 0;
    for (int k0 = 0; k0 < 512; k0 += 16) {
        const int nxt = cur ^ 1;
        const bool has = (k0 + 16) < 512;
        float4 va0, va1, vb0, vb1;
        if (has) {
            int kn = k0 + 16;
            va0 = (gr0 < M) ? *(const float4*)(A + (size_t)gr0 * 512 + kn + acol)
                            : make_float4(0.f,0.f,0.f,0.f);
            va1 = (gr1 < M) ? *(const float4*)(A + (size_t)gr1 * 512 + kn + acol)
                            : make_float4(0.f,0.f,0.f,0.f);
            vb0 = *(const float4*)(W + (size_t)(kn + brow    ) * 512 + col0 + bcol);
            vb1 = *(const float4*)(W + (size_t)(kn + brow + 8) * 512 + col0 + bcol);
        }
#pragma unroll
        for (int kk = 0; kk < 16; kk++) {
            float af[8];
            *(float4*)&af[0] = *(const float4*)&s->As[cur][kk][ty << 3];
            *(float4*)&af[4] = *(const float4*)&s->As[cur][kk][(ty << 3) + 4];
            const ull* bp = (const ull*)&s->Bs[cur][kk][tx << 3];
            ull b0 = bp[0], b1 = bp[1], b2 = bp[2], b3 = bp[3];
#pragma unroll
            for (int i = 0; i < 8; i++) {
                ull ad = fdup(af[i]);
                ffma2(acc2[i][0], ad, b0);
                ffma2(acc2[i][1], ad, b1);
                ffma2(acc2[i][2], ad, b2);
                ffma2(acc2[i][3], ad, b3);
            }
        }
        if (has) {
            s->As[nxt][acol+0][arow] = va0.x; s->As[nxt][acol+1][arow] = va0.y;
            s->As[nxt][acol+2][arow] = va0.z; s->As[nxt][acol+3][arow] = va0.w;
            s->As[nxt][acol+0][arow+64] = va1.x; s->As[nxt][acol+1][arow+64] = va1.y;
            s->As[nxt][acol+2][arow+64] = va1.z; s->As[nxt][acol+3][arow+64] = va1.w;
            *(float4*)&s->Bs[nxt][brow    ][bcol] = vb0;
            *(float4*)&s->Bs[nxt][brow + 8][bcol] = vb1;
            __syncthreads();
        }
        cur = nxt;
    }

#pragma unroll
    for (int i = 0; i < 8; i++) {
        int m = row0 + (ty << 3) + i;
        if (m >= M) continue;
#pragma unroll
        for (int j4 = 0; j4 < 2; j4++) {
            int n = col0 + (tx << 3) + (j4 << 2);
            float4 bb = bias ? *(const float4*)(bias + n) : make_float4(0.f,0.f,0.f,0.f);
            float2 pa = unpk(acc2[i][j4 * 2 + 0]);
            float2 pb = unpk(acc2[i][j4 * 2 + 1]);
            float4 o;
            o.x = pa.x + bb.x;
            o.y = pa.y + bb.y;
            o.z = pb.x + bb.z;
            o.w = pb.y + bb.w;
            if (MODE == 0) {
                *(float4*)(C + (size_t)m * 512 + n) = o;
            } else if (MODE == 1) {
                int b = m >> 10, t = m & 1023;
                int h = n >> 6,  d = n & 63;
                *(float4*)(C + ((size_t)((b << 3) + h) * NT + t) * NDH + d) = o;
            } else {
                int h = n >> 6, d = n & 63;
                *(float4*)(C + ((size_t)h * NSPOS + m) * NDH + d) = o;
            }
        }
    }
}

template<int MODE>
__global__ __launch_bounds__(256, 2)
void sgemm_k(const float* __restrict__ A, const float* __restrict__ W,
             const float* __restrict__ bias, float* __restrict__ C, int M)
{
    extern __shared__ char smraw[];
    sgemm_body<MODE>(A, W, bias, C, M, blockIdx.x << 7, blockIdx.y << 7,
                     (SmemGemm*)smraw);
}

// Fused Q/K/V projection: blockIdx.z selects weight/bias/destination.
__global__ __launch_bounds__(256, 2)
void sgemm_qkv_k(const float* __restrict__ x,
                 const float* __restrict__ Wq, const float* __restrict__ bq, float* __restrict__ Cq,
                 const float* __restrict__ Wk, const float* __restrict__ bk, float* __restrict__ Ck,
                 const float* __restrict__ Wv, const float* __restrict__ bv, float* __restrict__ Cv)
{
    extern __shared__ char smraw[];
    const float* W; const float* bias; float* C;
    if (blockIdx.z == 0)      { W = Wq; bias = bq; C = Cq; }
    else if (blockIdx.z == 1) { W = Wk; bias = bk; C = Ck; }
    else                      { W = Wv; bias = bv; C = Cv; }
    sgemm_body<1>(x, W, bias, C, NB * NT, blockIdx.x << 7, blockIdx.y << 7,
                  (SmemGemm*)smraw);
}

// ---------------------------------------------------------------------------
// Precompute uk[b,h,s] = pos_bias_u[h] . k[b,h,s]  and
//            vp[h,idx] = pos_bias_v[h] . p[h,idx].  One warp per row.
// ---------------------------------------------------------------------------
#define NUKROWS (NB*NH*NT)
#define NVPROWS (NH*NSPOS)
__global__ __launch_bounds__(256)
void biasdot_k(const float* __restrict__ k, const float* __restrict__ p,
               const float* __restrict__ pbu, const float* __restrict__ pbv,
               float* __restrict__ uk, float* __restrict__ vp)
{
    int w = (blockIdx.x * 256 + threadIdx.x) >> 5;
    int lane = threadIdx.x & 31;
    if (w < NUKROWS) {
        int h = (w >> 10) & 7;
        float2 a = *(const float2*)(k + (size_t)w * NDH + lane * 2);
        float2 u = *(const float2*)(pbu + h * NDH + lane * 2);
        float s = a.x * u.x + a.y * u.y;
#pragma unroll
        for (int off = 16; off >= 1; off >>= 1)
            s += __shfl_xor_sync(0xffffffffu, s, off);
        if (lane == 0) uk[w] = s;
    } else if (w < NUKROWS + NVPROWS) {
        int r = w - NUKROWS;
        float2 a = *(const float2*)(p + (size_t)r * NDH + lane * 2);
        int h = r / NSPOS;
        float2 u = *(const float2*)(pbv + h * NDH + lane * 2);
        float s = a.x * u.x + a.y * u.y;
#pragma unroll
        for (int off = 16; off >= 1; off >>= 1)
            s += __shfl_xor_sync(0xffffffffu, s, off);
        if (lane == 0) vp[r] = s;
    }
}

// ---------------------------------------------------------------------------
// Flash attention, 128 queries x 64 keys per tile, 256 threads,
// 8x4 fragments, f32x2 packed along the d (contraction) axis.
// score S[t,s] = q.k[s] + q.p[1023+s-t] + uk[s] + vp[1023+s-t], then *SCALE.
// ---------------------------------------------------------------------------
#define SQ_OFF 0
#define SK_OFF 8448            // 128*66
#define SV_OFF 12672           // + 64*66
#define SP_OFF 17024           // + 64*68
#define SPR_OFF 29630          // + 191*66
#define SUK_OFF 46270          // + 128*130
#define SVP_OFF 46334          // + 64
#define SM_FLOATS 46532        // + 191 (+ round)

__global__ __launch_bounds__(256)
void attn_k(const float* __restrict__ q, const float* __restrict__ k,
            const float* __restrict__ v, const float* __restrict__ p,
            const float* __restrict__ uk, const float* __restrict__ vp,
            float* __restrict__ out)
{
    extern __shared__ float sm[];
    float* sq  = sm + SQ_OFF;    // [128][66]
    float* sk_ = sm + SK_OFF;    // [64][66]
    float* sv_ = sm + SV_OFF;    // [64][68]
    float* sp_ = sm + SP_OFF;    // [191][66]
    float* sPs = sm + SPR_OFF;   // [128][130]
    float* suk = sm + SUK_OFF;   // [64]
    float* svp = sm + SVP_OFF;   // [191]

    const int tid = threadIdx.x;
    const int tx = tid >> 4;     // 0..15 (row group)
    const int ty = tid & 15;     // 0..15 (col group)
    const int bx = blockIdx.x;
    const int t0 = (bx & 7) << 7;
    const int bh = bx >> 3;
    const int h  = bh & 7;
    const int b  = bh >> 3;

    const float* qb = q + ((size_t)bh * NT + t0) * NDH;
    const float* kb = k + (size_t)bh * NT * NDH;
    const float* vb = v + (size_t)bh * NT * NDH;
    const float* pb = p + (size_t)h * NSPOS * NDH;

    // load q tile: 128 x 64
#pragma unroll
    for (int pp = 0; pp < 8; pp++) {
        int e = tid + (pp << 8);
        int r = e >> 4;
        int d4 = (e & 15) << 2;
        float4 t = *(const float4*)(qb + r * NDH + d4);
        sq[r*66 + d4 + 0] = t.x;
        sq[r*66 + d4 + 1] = t.y;
        sq[r*66 + d4 + 2] = t.z;
        sq[r*66 + d4 + 3] = t.w;
    }

    ull O2[8][2];
    float m_i[8], l_i[8];
#pragma unroll
    for (int i = 0; i < 8; i++) {
        m_i[i] = -3.0e38f;
        l_i[i] = 0.f;
        O2[i][0] = 0ull;
        O2[i][1] = 0ull;
    }

    const int pbrow = ty - tx + 15;   // band base row (dl = 0)

    for (int s0 = 0; s0 < NT; s0 += 64) {
        __syncthreads();   // prior AV / q store complete before overwrite
        // K, V tiles (64 x 64 each)
#pragma unroll
        for (int pp = 0; pp < 4; pp++) {
            int e = tid + (pp << 8);
            int r = e >> 4;
            int d4 = (e & 15) << 2;
            float4 kk = *(const float4*)(kb + (size_t)(s0 + r) * NDH + d4);
            sk_[r*66+d4+0] = kk.x; sk_[r*66+d4+1] = kk.y;
            sk_[r*66+d4+2] = kk.z; sk_[r*66+d4+3] = kk.w;
            float4 vv = *(const float4*)(vb + (size_t)(s0 + r) * NDH + d4);
            sv_[r*68+d4+0] = vv.x; sv_[r*68+d4+1] = vv.y;
            sv_[r*68+d4+2] = vv.z; sv_[r*68+d4+3] = vv.w;
        }
        // p band: 191 rows, global index pbase + jj, always in [0,2046]
        const int pbase = 896 + s0 - t0;
#pragma unroll
        for (int pp = 0; pp < 12; pp++) {
            int e = tid + (pp << 8);
            if (e < 191 * 16) {
                int r = e >> 4;
                int d4 = (e & 15) << 2;
                float4 pv4 = *(const float4*)(pb + (size_t)(pbase + r) * NDH + d4);
                sp_[r*66+d4+0] = pv4.x; sp_[r*66+d4+1] = pv4.y;
                sp_[r*66+d4+2] = pv4.z; sp_[r*66+d4+3] = pv4.w;
            }
        }
        if (tid < 64)  suk[tid] = uk[bh * NT + s0 + tid];
        if (tid < 191) svp[tid] = vp[h * NSPOS + pbase + tid];
        __syncthreads();

        // ---- scores (f32x2 packed along d) ----
        ull S2[8][4];
#pragma unroll
        for (int i = 0; i < 8; i++)
#pragma unroll
            for (int j = 0; j < 4; j++) S2[i][j] = 0ull;

#pragma unroll 4
        for (int d2 = 0; d2 < 64; d2 += 2) {
            ull qp[8], kp[4], pv[11];
#pragma unroll
            for (int i = 0; i < 8; i++)
                qp[i] = *(const ull*)(sq + (tx + (i << 4)) * 66 + d2);
#pragma unroll
            for (int j = 0; j < 4; j++)
                kp[j] = *(const ull*)(sk_ + (ty + (j << 4)) * 66 + d2);
#pragma unroll
            for (int dl = 0; dl < 11; dl++)
                pv[dl] = *(const ull*)(sp_ + (pbrow + (dl << 4)) * 66 + d2);
#pragma unroll
            for (int i = 0; i < 8; i++)
#pragma unroll
                for (int j = 0; j < 4; j++) {
                    ffma2(S2[i][j], qp[i], kp[j]);
                    ffma2(S2[i][j], qp[i], pv[j - i + 7]);
                }
        }

        // ---- online softmax (rows owned by 16-lane groups) ----
#pragma unroll
        for (int i = 0; i < 8; i++) {
            float s[4];
            float mt = -3.0e38f;
#pragma unroll
            for (int j = 0; j < 4; j++) {
                float2 f = unpk(S2[i][j]);
                s[j] = (f.x + f.y + suk[ty + (j << 4)]
                        + svp[pbrow + ((j - i + 7) << 4)]) * ATT_SCALE;
                mt = fmaxf(mt, s[j]);
            }
#pragma unroll
            for (int off = 8; off >= 1; off >>= 1)
                mt = fmaxf(mt, __shfl_xor_sync(0xffffffffu, mt, off));
            float mn = fmaxf(m_i[i], mt);
            float alpha = __expf(m_i[i] - mn);
            m_i[i] = mn;
            float rs = 0.f;
#pragma unroll
            for (int j = 0; j < 4; j++) {
                float ev = __expf(s[j] - mn);
                s[j] = ev;
                rs += ev;
            }
#pragma unroll
            for (int off = 8; off >= 1; off >>= 1)
                rs += __shfl_xor_sync(0xffffffffu, rs, off);
            l_i[i] = l_i[i] * alpha + rs;
            ull ad = fdup(alpha);
            fmul2(O2[i][0], ad);
            fmul2(O2[i][1], ad);
#pragma unroll
            for (int j = 0; j < 4; j++)
                sPs[(tx + (i << 4)) * 130 + ty + (j << 4)] = s[j];
        }
        __syncthreads();

        // ---- O += P @ V (f32x2 packed along d) ----
#pragma unroll 4
        for (int c = 0; c < 64; c++) {
            const ull* vrow = (const ull*)(sv_ + c * 68 + (ty << 2));
            ull v0 = vrow[0], v1 = vrow[1];
#pragma unroll
            for (int i = 0; i < 8; i++) {
                ull pd = fdup(sPs[(tx + (i << 4)) * 130 + c]);
                ffma2(O2[i][0], pd, v0);
                ffma2(O2[i][1], pd, v1);
            }
        }
    }

    // normalize, write to [b][t][h*64+d]
#pragma unroll
    for (int i = 0; i < 8; i++) {
        float inv = 1.f / l_i[i];
        float2 a = unpk(O2[i][0]);
        float2 c2 = unpk(O2[i][1]);
        float4 o;
        o.x = a.x * inv;  o.y = a.y * inv;
        o.z = c2.x * inv; o.w = c2.y * inv;
        int r = tx + (i << 4);
        *(float4*)(out + ((size_t)b * NT + t0 + r) * ND + h * NDH + (ty << 2)) = o;
    }
}

// ---------------------------------------------------------------------------
extern "C" void kernel_launch(void* const* d_in, const int* in_sizes, int n_in,
                              void* d_out, int out_size)
{
    const float* x    = (const float*)d_in[0];
    const float* pe   = (const float*)d_in[1];
    const float* Wq   = (const float*)d_in[2];
    const float* bq   = (const float*)d_in[3];
    const float* Wk   = (const float*)d_in[4];
    const float* bk   = (const float*)d_in[5];
    const float* Wv   = (const float*)d_in[6];
    const float* bv   = (const float*)d_in[7];
    const float* Wpos = (const float*)d_in[8];
    const float* pbu  = (const float*)d_in[9];
    const float* pbv  = (const float*)d_in[10];
    const float* Wo   = (const float*)d_in[11];
    const float* bo   = (const float*)d_in[12];
    float* out = (float*)d_out;

    float *qp, *kp, *vp_, *pp, *aop, *ukp, *vpp;
    cudaGetSymbolAddress((void**)&qp,  g_q);
    cudaGetSymbolAddress((void**)&kp,  g_k);
    cudaGetSymbolAddress((void**)&vp_, g_v);
    cudaGetSymbolAddress((void**)&pp,  g_p);
    cudaGetSymbolAddress((void**)&aop, g_ao);
    cudaGetSymbolAddress((void**)&ukp, g_uk);
    cudaGetSymbolAddress((void**)&vpp, g_vp);

    const int gsm = (int)sizeof(SmemGemm);                  // 67584 B
    cudaFuncSetAttribute(sgemm_qkv_k, cudaFuncAttributeMaxDynamicSharedMemorySize, gsm);
    cudaFuncSetAttribute(sgemm_k<0>,  cudaFuncAttributeMaxDynamicSharedMemorySize, gsm);
    cudaFuncSetAttribute(sgemm_k<2>,  cudaFuncAttributeMaxDynamicSharedMemorySize, gsm);
    const int smem = SM_FLOATS * (int)sizeof(float);        // 186128 B
    cudaFuncSetAttribute(attn_k, cudaFuncAttributeMaxDynamicSharedMemorySize, smem);

    dim3 blk(256);
    sgemm_qkv_k<<<dim3(64, 4, 3), blk, gsm>>>(x, Wq, bq, qp, Wk, bk, kp, Wv, bv, vp_);
    sgemm_k<2><<<dim3(16, 4), blk, gsm>>>(pe, Wpos, nullptr, pp, NSPOS);
    biasdot_k<<<(NUKROWS + NVPROWS + 7) / 8, blk>>>(kp, pp, pbu, pbv, ukp, vpp);
    attn_k<<<NB * NH * (NT / 128), blk, smem>>>(qp, kp, vp_, pp, ukp, vpp, aop);
    sgemm_k<0><<<dim3(64, 4), blk, gsm>>>(aop, Wo, bo, out, NB * NT);
}

// round 9
// speedup vs baseline: 1.3455x; 1.0968x over previous
#include <cuda_runtime.h>

#define NB 8
#define NT 1024
#define ND 512
#define NH 8
#define NDH 64
#define NSPOS 2047
#define ATT_SCALE 0.125f

typedef unsigned long long ull;

// Scratch (device globals; no allocations allowed)
__device__ float g_q[NB*NH*NT*NDH];
__device__ float g_k[NB*NH*NT*NDH];
__device__ float g_v[NB*NH*NT*NDH];
__device__ float g_p[NH*NSPOS*NDH];
__device__ float g_ao[NB*NT*ND];
__device__ float g_uk[NB*NH*NT];
__device__ float g_vp[NH*NSPOS];

__device__ __forceinline__ void ffma2(ull &d, ull a, ull b) {
    asm("fma.rn.f32x2 %0, %1, %2, %0;" : "+l"(d) : "l"(a), "l"(b));
}
__device__ __forceinline__ void fmul2(ull &d, ull a) {
    asm("mul.rn.f32x2 %0, %0, %1;" : "+l"(d) : "l"(a));
}
__device__ __forceinline__ ull fdup(float x) {
    ull r; asm("mov.b64 %0, {%1, %1};" : "=l"(r) : "f"(x)); return r;
}
__device__ __forceinline__ float2 unpk(ull v) {
    float2 f; asm("mov.b64 {%0, %1}, %2;" : "=f"(f.x), "=f"(f.y) : "l"(v)); return f;
}

// ---------------------------------------------------------------------------
// Double-buffered SGEMM body. C[M,512] = A[M,512] @ W[512,512] (+bias).
// 128x128 tile, BK=16, 256 thr, 8x8 fragments as 8x4 f32x2 pairs.
// ---------------------------------------------------------------------------
struct SmemGemm {
    float As[2][16][132];
    float Bs[2][16][132];
};

template<int MODE>
__device__ __forceinline__
void sgemm_body(const float* __restrict__ A, const float* __restrict__ W,
                const float* __restrict__ bias, float* __restrict__ C,
                int M, int row0, int col0, SmemGemm* s)
{
    const int tid = threadIdx.x;
    const int tx = tid & 15;
    const int ty = tid >> 4;

    ull acc2[8][4];
#pragma unroll
    for (int i = 0; i < 8; i++)
#pragma unroll
        for (int j = 0; j < 4; j++) acc2[i][j] = 0ull;

    const int arow = tid >> 2;
    const int acol = (tid & 3) << 2;
    const int brow = tid >> 5;
    const int bcol = (tid & 31) << 2;
    const int gr0 = row0 + arow;
    const int gr1 = row0 + arow + 64;

    // preload slice 0 into buffer 0
    {
        float4 va0 = (gr0 < M) ? *(const float4*)(A + (size_t)gr0 * 512 + acol)
                               : make_float4(0.f,0.f,0.f,0.f);
        float4 va1 = (gr1 < M) ? *(const float4*)(A + (size_t)gr1 * 512 + acol)
                               : make_float4(0.f,0.f,0.f,0.f);
        s->As[0][acol+0][arow] = va0.x; s->As[0][acol+1][arow] = va0.y;
        s->As[0][acol+2][arow] = va0.z; s->As[0][acol+3][arow] = va0.w;
        s->As[0][acol+0][arow+64] = va1.x; s->As[0][acol+1][arow+64] = va1.y;
        s->As[0][acol+2][arow+64] = va1.z; s->As[0][acol+3][arow+64] = va1.w;
        *(float4*)&s->Bs[0][brow    ][bcol] = *(const float4*)(W + (size_t)(brow    ) * 512 + col0 + bcol);
        *(float4*)&s->Bs[0][brow + 8][bcol] = *(const float4*)(W + (size_t)(brow + 8) * 512 + col0 + bcol);
    }
    __syncthreads();

    int cur = 0;
    for (int k0 = 0; k0 < 512; k0 += 16) {
        const int nxt = cur ^ 1;
        const bool has = (k0 + 16) < 512;
        float4 va0, va1, vb0, vb1;
        if (has) {
            int kn = k0 + 16;
            va0 = (gr0 < M) ? *(const float4*)(A + (size_t)gr0 * 512 + kn + acol)
                            : make_float4(0.f,0.f,0.f,0.f);
            va1 = (gr1 < M) ? *(const float4*)(A + (size_t)gr1 * 512 + kn + acol)
                            : make_float4(0.f,0.f,0.f,0.f);
            vb0 = *(const float4*)(W + (size_t)(kn + brow    ) * 512 + col0 + bcol);
            vb1 = *(const float4*)(W + (size_t)(kn + brow + 8) * 512 + col0 + bcol);
        }
#pragma unroll
        for (int kk = 0; kk < 16; kk++) {
            float af[8];
            *(float4*)&af[0] = *(const float4*)&s->As[cur][kk][ty << 3];
            *(float4*)&af[4] = *(const float4*)&s->As[cur][kk][(ty << 3) + 4];
            const ull* bp = (const ull*)&s->Bs[cur][kk][tx << 3];
            ull b0 = bp[0], b1 = bp[1], b2 = bp[2], b3 = bp[3];
#pragma unroll
            for (int i = 0; i < 8; i++) {
                ull ad = fdup(af[i]);
                ffma2(acc2[i][0], ad, b0);
                ffma2(acc2[i][1], ad, b1);
                ffma2(acc2[i][2], ad, b2);
                ffma2(acc2[i][3], ad, b3);
            }
        }
        if (has) {
            s->As[nxt][acol+0][arow] = va0.x; s->As[nxt][acol+1][arow] = va0.y;
            s->As[nxt][acol+2][arow] = va0.z; s->As[nxt][acol+3][arow] = va0.w;
            s->As[nxt][acol+0][arow+64] = va1.x; s->As[nxt][acol+1][arow+64] = va1.y;
            s->As[nxt][acol+2][arow+64] = va1.z; s->As[nxt][acol+3][arow+64] = va1.w;
            *(float4*)&s->Bs[nxt][brow    ][bcol] = vb0;
            *(float4*)&s->Bs[nxt][brow + 8][bcol] = vb1;
            __syncthreads();
        }
        cur = nxt;
    }

#pragma unroll
    for (int i = 0; i < 8; i++) {
        int m = row0 + (ty << 3) + i;
        if (m >= M) continue;
#pragma unroll
        for (int j4 = 0; j4 < 2; j4++) {
            int n = col0 + (tx << 3) + (j4 << 2);
            float4 bb = bias ? *(const float4*)(bias + n) : make_float4(0.f,0.f,0.f,0.f);
            float2 pa = unpk(acc2[i][j4 * 2 + 0]);
            float2 pb = unpk(acc2[i][j4 * 2 + 1]);
            float4 o;
            o.x = pa.x + bb.x;
            o.y = pa.y + bb.y;
            o.z = pb.x + bb.z;
            o.w = pb.y + bb.w;
            if (MODE == 0) {
                *(float4*)(C + (size_t)m * 512 + n) = o;
            } else if (MODE == 1) {
                int b = m >> 10, t = m & 1023;
                int h = n >> 6,  d = n & 63;
                *(float4*)(C + ((size_t)((b << 3) + h) * NT + t) * NDH + d) = o;
            } else {
                int h = n >> 6, d = n & 63;
                *(float4*)(C + ((size_t)h * NSPOS + m) * NDH + d) = o;
            }
        }
    }
}

template<int MODE>
__global__ __launch_bounds__(256, 2)
void sgemm_k(const float* __restrict__ A, const float* __restrict__ W,
             const float* __restrict__ bias, float* __restrict__ C, int M)
{
    extern __shared__ char smraw[];
    sgemm_body<MODE>(A, W, bias, C, M, blockIdx.x << 7, blockIdx.y << 7,
                     (SmemGemm*)smraw);
}

// Fused Q/K/V/Pos projection: blockIdx.z selects the GEMM.
// z==3 is the pos projection (M=2047 -> only 16 x-blocks active).
__global__ __launch_bounds__(256, 2)
void sgemm_fused_k(const float* __restrict__ x,
                   const float* __restrict__ Wq, const float* __restrict__ bq, float* __restrict__ Cq,
                   const float* __restrict__ Wk, const float* __restrict__ bk, float* __restrict__ Ck,
                   const float* __restrict__ Wv, const float* __restrict__ bv, float* __restrict__ Cv,
                   const float* __restrict__ pe, const float* __restrict__ Wpos, float* __restrict__ Cp)
{
    extern __shared__ char smraw[];
    const int z = blockIdx.z;
    if (z == 3) {
        if (blockIdx.x >= 16) return;
        sgemm_body<2>(pe, Wpos, nullptr, Cp, NSPOS,
                      blockIdx.x << 7, blockIdx.y << 7, (SmemGemm*)smraw);
    } else {
        const float* W; const float* bias; float* C;
        if (z == 0)      { W = Wq; bias = bq; C = Cq; }
        else if (z == 1) { W = Wk; bias = bk; C = Ck; }
        else             { W = Wv; bias = bv; C = Cv; }
        sgemm_body<1>(x, W, bias, C, NB * NT,
                      blockIdx.x << 7, blockIdx.y << 7, (SmemGemm*)smraw);
    }
}

// ---------------------------------------------------------------------------
// Precompute uk[b,h,s] = pos_bias_u[h] . k[b,h,s]  and
//            vp[h,idx] = pos_bias_v[h] . p[h,idx].  One warp per row.
// ---------------------------------------------------------------------------
#define NUKROWS (NB*NH*NT)
#define NVPROWS (NH*NSPOS)
__global__ __launch_bounds__(256)
void biasdot_k(const float* __restrict__ k, const float* __restrict__ p,
               const float* __restrict__ pbu, const float* __restrict__ pbv,
               float* __restrict__ uk, float* __restrict__ vp)
{
    int w = (blockIdx.x * 256 + threadIdx.x) >> 5;
    int lane = threadIdx.x & 31;
    if (w < NUKROWS) {
        int h = (w >> 10) & 7;
        float2 a = *(const float2*)(k + (size_t)w * NDH + lane * 2);
        float2 u = *(const float2*)(pbu + h * NDH + lane * 2);
        float s = a.x * u.x + a.y * u.y;
#pragma unroll
        for (int off = 16; off >= 1; off >>= 1)
            s += __shfl_xor_sync(0xffffffffu, s, off);
        if (lane == 0) uk[w] = s;
    } else if (w < NUKROWS + NVPROWS) {
        int r = w - NUKROWS;
        float2 a = *(const float2*)(p + (size_t)r * NDH + lane * 2);
        int h = r / NSPOS;
        float2 u = *(const float2*)(pbv + h * NDH + lane * 2);
        float s = a.x * u.x + a.y * u.y;
#pragma unroll
        for (int off = 16; off >= 1; off >>= 1)
            s += __shfl_xor_sync(0xffffffffu, s, off);
        if (lane == 0) vp[r] = s;
    }
}

// ---------------------------------------------------------------------------
// Flash attention, 128 queries x 64 keys per tile, 256 threads, 8x4 frags,
// f32x2 packed along d. Score loop uses LDS.128 (ulonglong2) from XOR-swizzled
// smem (stride 64 floats, float4-column c4' = c4 ^ (row & 15)).
// score S[t,s] = q.k[s] + q.p[1023+s-t] + uk[s] + vp[1023+s-t], then *SCALE.
// ---------------------------------------------------------------------------
#define SQ_OFF 0               // [128][64] swizzled
#define SK_OFF 8192            // [64][64] swizzled
#define SP_OFF 12288           // [191][64] swizzled
#define SV_OFF 24512           // [64][68] linear
#define SPR_OFF 28864          // [128][130]
#define SUK_OFF 45504          // [64]
#define SVP_OFF 45568          // [191]
#define SM_FLOATS 45760

__global__ __launch_bounds__(256)
void attn_k(const float* __restrict__ q, const float* __restrict__ k,
            const float* __restrict__ v, const float* __restrict__ p,
            const float* __restrict__ uk, const float* __restrict__ vp,
            float* __restrict__ out)
{
    extern __shared__ float sm[];
    float* sq  = sm + SQ_OFF;
    float* sk_ = sm + SK_OFF;
    float* sp_ = sm + SP_OFF;
    float* sv_ = sm + SV_OFF;
    float* sPs = sm + SPR_OFF;
    float* suk = sm + SUK_OFF;
    float* svp = sm + SVP_OFF;

    const int tid = threadIdx.x;
    const int tx = tid >> 4;     // 0..15 (row group)
    const int ty = tid & 15;     // 0..15 (col group)
    const int bx = blockIdx.x;
    const int t0 = (bx & 7) << 7;
    const int bh = bx >> 3;
    const int h  = bh & 7;
    const int b  = bh >> 3;

    const float* qb = q + ((size_t)bh * NT + t0) * NDH;
    const float* kb = k + (size_t)bh * NT * NDH;
    const float* vb = v + (size_t)bh * NT * NDH;
    const float* pb = p + (size_t)h * NSPOS * NDH;

    // load q tile (swizzled): 128 rows x 16 float4-cols
#pragma unroll
    for (int pp = 0; pp < 8; pp++) {
        int e = tid + (pp << 8);
        int r = e >> 4;
        int c4 = e & 15;
        float4 t = *(const float4*)(qb + r * NDH + (c4 << 2));
        *(float4*)(sq + r * 64 + (((c4 ^ (r & 15)) << 2))) = t;
    }

    ull O2[8][2];
    float m_i[8], l_i[8];
#pragma unroll
    for (int i = 0; i < 8; i++) {
        m_i[i] = -3.0e38f;
        l_i[i] = 0.f;
        O2[i][0] = 0ull;
        O2[i][1] = 0ull;
    }

    const int pbrow = ty - tx + 15;   // band base row (dl = 0)
    const int pb15  = pbrow & 15;

    for (int s0 = 0; s0 < NT; s0 += 64) {
        __syncthreads();   // prior AV / q store complete before overwrite
        // K (swizzled) and V (linear) tiles
#pragma unroll
        for (int pp = 0; pp < 4; pp++) {
            int e = tid + (pp << 8);
            int r = e >> 4;
            int c4 = e & 15;
            float4 kk = *(const float4*)(kb + (size_t)(s0 + r) * NDH + (c4 << 2));
            *(float4*)(sk_ + r * 64 + ((c4 ^ (r & 15)) << 2)) = kk;
            float4 vv = *(const float4*)(vb + (size_t)(s0 + r) * NDH + (c4 << 2));
            *(float4*)(sv_ + r * 68 + (c4 << 2)) = vv;
        }
        // p band (swizzled): 191 rows, global index pbase + r in [0,2046]
        const int pbase = 896 + s0 - t0;
#pragma unroll
        for (int pp = 0; pp < 12; pp++) {
            int e = tid + (pp << 8);
            if (e < 191 * 16) {
                int r = e >> 4;
                int c4 = e & 15;
                float4 pv4 = *(const float4*)(pb + (size_t)(pbase + r) * NDH + (c4 << 2));
                *(float4*)(sp_ + r * 64 + ((c4 ^ (r & 15)) << 2)) = pv4;
            }
        }
        if (tid < 64)  suk[tid] = uk[bh * NT + s0 + tid];
        if (tid < 191) svp[tid] = vp[h * NSPOS + pbase + tid];
        __syncthreads();

        // ---- scores: LDS.128 loads, f32x2 FMAs ----
        ull S2[8][4];
#pragma unroll
        for (int i = 0; i < 8; i++)
#pragma unroll
            for (int j = 0; j < 4; j++) S2[i][j] = 0ull;

#pragma unroll 2
        for (int c4 = 0; c4 < 16; c4++) {
            ulonglong2 qv[8], kv[4], pv[11];
            const int qoff = (c4 ^ tx) << 2;
            const int koff = (c4 ^ ty) << 2;
            const int poff = (c4 ^ pb15) << 2;
#pragma unroll
            for (int i = 0; i < 8; i++)
                qv[i] = *(const ulonglong2*)(sq + (tx + (i << 4)) * 64 + qoff);
#pragma unroll
            for (int j = 0; j < 4; j++)
                kv[j] = *(const ulonglong2*)(sk_ + (ty + (j << 4)) * 64 + koff);
#pragma unroll
            for (int dl = 0; dl < 11; dl++)
                pv[dl] = *(const ulonglong2*)(sp_ + (pbrow + (dl << 4)) * 64 + poff);
#pragma unroll
            for (int i = 0; i < 8; i++)
#pragma unroll
                for (int j = 0; j < 4; j++) {
                    ffma2(S2[i][j], qv[i].x, kv[j].x);
                    ffma2(S2[i][j], qv[i].y, kv[j].y);
                    ffma2(S2[i][j], qv[i].x, pv[j - i + 7].x);
                    ffma2(S2[i][j], qv[i].y, pv[j - i + 7].y);
                }
        }

        // ---- online softmax (rows owned by 16-lane groups) ----
#pragma unroll
        for (int i = 0; i < 8; i++) {
            float s[4];
            float mt = -3.0e38f;
#pragma unroll
            for (int j = 0; j < 4; j++) {
                float2 f = unpk(S2[i][j]);
                s[j] = (f.x + f.y + suk[ty + (j << 4)]
                        + svp[pbrow + ((j - i + 7) << 4)]) * ATT_SCALE;
                mt = fmaxf(mt, s[j]);
            }
#pragma unroll
            for (int off = 8; off >= 1; off >>= 1)
                mt = fmaxf(mt, __shfl_xor_sync(0xffffffffu, mt, off));
            float mn = fmaxf(m_i[i], mt);
            float alpha = __expf(m_i[i] - mn);
            m_i[i] = mn;
            float rs = 0.f;
#pragma unroll
            for (int j = 0; j < 4; j++) {
                float ev = __expf(s[j] - mn);
                s[j] = ev;
                rs += ev;
            }
#pragma unroll
            for (int off = 8; off >= 1; off >>= 1)
                rs += __shfl_xor_sync(0xffffffffu, rs, off);
            l_i[i] = l_i[i] * alpha + rs;
            ull ad = fdup(alpha);
            fmul2(O2[i][0], ad);
            fmul2(O2[i][1], ad);
#pragma unroll
            for (int j = 0; j < 4; j++)
                sPs[(tx + (i << 4)) * 130 + ty + (j << 4)] = s[j];
        }
        __syncthreads();

        // ---- O += P @ V ----
#pragma unroll 4
        for (int c = 0; c < 64; c++) {
            ulonglong2 vv = *(const ulonglong2*)(sv_ + c * 68 + (ty << 2));
#pragma unroll
            for (int i = 0; i < 8; i++) {
                ull pd = fdup(sPs[(tx + (i << 4)) * 130 + c]);
                ffma2(O2[i][0], pd, vv.x);
                ffma2(O2[i][1], pd, vv.y);
            }
        }
    }

    // normalize, write to [b][t][h*64+d]
#pragma unroll
    for (int i = 0; i < 8; i++) {
        float inv = 1.f / l_i[i];
        float2 a = unpk(O2[i][0]);
        float2 c2 = unpk(O2[i][1]);
        float4 o;
        o.x = a.x * inv;  o.y = a.y * inv;
        o.z = c2.x * inv; o.w = c2.y * inv;
        int r = tx + (i << 4);
        *(float4*)(out + ((size_t)b * NT + t0 + r) * ND + h * NDH + (ty << 2)) = o;
    }
}

// ---------------------------------------------------------------------------
extern "C" void kernel_launch(void* const* d_in, const int* in_sizes, int n_in,
                              void* d_out, int out_size)
{
    const float* x    = (const float*)d_in[0];
    const float* pe   = (const float*)d_in[1];
    const float* Wq   = (const float*)d_in[2];
    const float* bq   = (const float*)d_in[3];
    const float* Wk   = (const float*)d_in[4];
    const float* bk   = (const float*)d_in[5];
    const float* Wv   = (const float*)d_in[6];
    const float* bv   = (const float*)d_in[7];
    const float* Wpos = (const float*)d_in[8];
    const float* pbu  = (const float*)d_in[9];
    const float* pbv  = (const float*)d_in[10];
    const float* Wo   = (const float*)d_in[11];
    const float* bo   = (const float*)d_in[12];
    float* out = (float*)d_out;

    float *qp, *kp, *vp_, *pp, *aop, *ukp, *vpp;
    cudaGetSymbolAddress((void**)&qp,  g_q);
    cudaGetSymbolAddress((void**)&kp,  g_k);
    cudaGetSymbolAddress((void**)&vp_, g_v);
    cudaGetSymbolAddress((void**)&pp,  g_p);
    cudaGetSymbolAddress((void**)&aop, g_ao);
    cudaGetSymbolAddress((void**)&ukp, g_uk);
    cudaGetSymbolAddress((void**)&vpp, g_vp);

    const int gsm = (int)sizeof(SmemGemm);                  // 67584 B
    cudaFuncSetAttribute(sgemm_fused_k, cudaFuncAttributeMaxDynamicSharedMemorySize, gsm);
    cudaFuncSetAttribute(sgemm_k<0>,    cudaFuncAttributeMaxDynamicSharedMemorySize, gsm);
    const int smem = SM_FLOATS * (int)sizeof(float);        // 183040 B
    cudaFuncSetAttribute(attn_k, cudaFuncAttributeMaxDynamicSharedMemorySize, smem);

    dim3 blk(256);
    sgemm_fused_k<<<dim3(64, 4, 4), blk, gsm>>>(x, Wq, bq, qp, Wk, bk, kp,
                                                Wv, bv, vp_, pe, Wpos, pp);
    biasdot_k<<<(NUKROWS + NVPROWS + 7) / 8, blk>>>(kp, pp, pbu, pbv, ukp, vpp);
    attn_k<<<NB * NH * (NT / 128), blk, smem>>>(qp, kp, vp_, pp, ukp, vpp, aop);
    sgemm_k<0><<<dim3(64, 4), blk, gsm>>>(aop, Wo, bo, out, NB * NT);
}

// round 11
// speedup vs baseline: 1.5805x; 1.1746x over previous
#include <cuda_runtime.h>
#include <cuda_bf16.h>
#include <cstdint>

#define NB 8
#define NT 1024
#define ND 512
#define NH 8
#define NDH 64
#define NSPOS 2047
#define ATT_SCALE 0.125f

typedef unsigned long long ull;

// ---------------- scratch (device globals; no allocs allowed) ----------------
__device__ float g_q[NB*NH*NT*NDH];
__device__ float g_k[NB*NH*NT*NDH];
__device__ float g_v[NB*NH*NT*NDH];
__device__ float g_p[NH*NSPOS*NDH];
__device__ float g_ao[NB*NT*ND];
__device__ float g_uk[NB*NH*NT];
__device__ float g_vp[NH*NSPOS];
__device__ __nv_bfloat16 g_xh[NB*NT*ND],  g_xl[NB*NT*ND];
__device__ __nv_bfloat16 g_peh[2048*ND],  g_pel[2048*ND];
__device__ __nv_bfloat16 g_wth[5*ND*ND],  g_wtl[5*ND*ND];
__device__ __nv_bfloat16 g_aoh[NB*NT*ND], g_aol[NB*NT*ND];

// ---------------- scalar f32x2 helpers (attention) ----------------
__device__ __forceinline__ void ffma2(ull &d, ull a, ull b) {
    asm("fma.rn.f32x2 %0, %1, %2, %0;" : "+l"(d) : "l"(a), "l"(b));
}
__device__ __forceinline__ void fmul2(ull &d, ull a) {
    asm("mul.rn.f32x2 %0, %0, %1;" : "+l"(d) : "l"(a));
}
__device__ __forceinline__ ull fdup(float x) {
    ull r; asm("mov.b64 %0, {%1, %1};" : "=l"(r) : "f"(x)); return r;
}
__device__ __forceinline__ float2 unpk(ull v) {
    float2 f; asm("mov.b64 {%0, %1}, %2;" : "=f"(f.x), "=f"(f.y) : "l"(v)); return f;
}

// ---------------- mma.sync / ldmatrix / cp.async helpers (sm_80+, compute_103-legal) ----
__device__ __forceinline__ uint32_t smem_u32(const void* p) {
    uint32_t a;
    asm("{ .reg .u64 t; cvta.to.shared.u64 t, %1; cvt.u32.u64 %0, t; }" : "=r"(a) : "l"(p));
    return a;
}
#define LDSM4(r, addr) \
    asm volatile("ldmatrix.sync.aligned.m8n8.x4.shared.b16 {%0,%1,%2,%3}, [%4];" \
        : "=r"((r)[0]), "=r"((r)[1]), "=r"((r)[2]), "=r"((r)[3]) : "r"(addr))
#define MMA16816(c, a, b0, b1) \
    asm volatile("mma.sync.aligned.m16n8k16.row.col.f32.bf16.bf16.f32 " \
        "{%0,%1,%2,%3}, {%4,%5,%6,%7}, {%8,%9}, {%0,%1,%2,%3};" \
        : "+f"((c)[0]), "+f"((c)[1]), "+f"((c)[2]), "+f"((c)[3]) \
        : "r"((a)[0]), "r"((a)[1]), "r"((a)[2]), "r"((a)[3]), "r"(b0), "r"(b1))
__device__ __forceinline__ void cpa16(uint32_t dst, const void* src, int sz) {
    asm volatile("cp.async.cg.shared.global [%0], [%1], 16, %2;"
                 :: "r"(dst), "l"(src), "r"(sz) : "memory");
}
__device__ __forceinline__ void cpa_commit() {
    asm volatile("cp.async.commit_group;" ::: "memory");
}
__device__ __forceinline__ void cpa_wait0() {
    asm volatile("cp.async.wait_group 0;" ::: "memory");
}

// ---------------- split-precision convert kernels ----------------
__global__ __launch_bounds__(256)
void split_k(const float* __restrict__ s, __nv_bfloat16* __restrict__ h,
             __nv_bfloat16* __restrict__ l, int n4)
{
    int i = blockIdx.x * 256 + threadIdx.x;
    if (i >= n4) return;
    float4 v = ((const float4*)s)[i];
    __nv_bfloat16 h0 = __float2bfloat16(v.x), h1 = __float2bfloat16(v.y);
    __nv_bfloat16 h2 = __float2bfloat16(v.z), h3 = __float2bfloat16(v.w);
    __nv_bfloat16 l0 = __float2bfloat16(v.x - __bfloat162float(h0));
    __nv_bfloat16 l1 = __float2bfloat16(v.y - __bfloat162float(h1));
    __nv_bfloat16 l2 = __float2bfloat16(v.z - __bfloat162float(h2));
    __nv_bfloat16 l3 = __float2bfloat16(v.w - __bfloat162float(h3));
    ((__nv_bfloat162*)h)[i*2+0] = __nv_bfloat162(h0, h1);
    ((__nv_bfloat162*)h)[i*2+1] = __nv_bfloat162(h2, h3);
    ((__nv_bfloat162*)l)[i*2+0] = __nv_bfloat162(l0, l1);
    ((__nv_bfloat162*)l)[i*2+1] = __nv_bfloat162(l2, l3);
}

// Transpose + split the 5 weight matrices: wt[z][n][k] = W_z[k][n]
__global__ __launch_bounds__(256)
void wsplit_k(const float* __restrict__ W0, const float* __restrict__ W1,
              const float* __restrict__ W2, const float* __restrict__ W3,
              const float* __restrict__ W4,
              __nv_bfloat16* __restrict__ th, __nv_bfloat16* __restrict__ tl)
{
    const float* W;
    switch (blockIdx.z) {
        case 0: W = W0; break;
        case 1: W = W1; break;
        case 2: W = W2; break;
        case 3: W = W3; break;
        default: W = W4; break;
    }
    __shared__ float t[32][33];
    int tx = threadIdx.x & 31, ty = threadIdx.x >> 5;
    int n0 = blockIdx.x * 32, k0 = blockIdx.y * 32;
#pragma unroll
    for (int ph = 0; ph < 4; ph++)
        t[ty + ph * 8][tx] = W[(size_t)(k0 + ty + ph * 8) * ND + n0 + tx];
    __syncthreads();
    size_t base = (size_t)blockIdx.z * ND * ND;
#pragma unroll
    for (int ph = 0; ph < 4; ph++) {
        int n = n0 + ty + ph * 8, k = k0 + tx;
        float v = t[tx][ty + ph * 8];
        __nv_bfloat16 hh = __float2bfloat16(v);
        __nv_bfloat16 ll = __float2bfloat16(v - __bfloat162float(hh));
        th[base + (size_t)n * ND + k] = hh;
        tl[base + (size_t)n * ND + k] = ll;
    }
}

// ---------------------------------------------------------------------------
// mma.sync split-bf16 GEMM: C[M,512] = (Ah+Al) @ (Bh+Bl)^T (+bias).
// B pre-transposed K-major ([n][k]). 128x128 tile, 256 thr (8 warps, 2x4),
// each warp 64x32 via 4x4 m16n8k16 frags. BK=32, cp.async double buffer.
// Smem rows padded to 40 bf16 (80B stride -> ldmatrix conflict-free).
//   MODE 0: row-major;  MODE 1: [b][h][t][d];  MODE 2: [h][m][d]
// ---------------------------------------------------------------------------
#define MT_AH 0
#define MT_AL 10240
#define MT_BH 20480
#define MT_BL 30720
#define MT_BUF 40960
#define MT_SMEM 81920

template<int MODE>
__device__ __forceinline__
void mmagemm_body(const __nv_bfloat16* __restrict__ Ah, const __nv_bfloat16* __restrict__ Al,
                  const __nv_bfloat16* __restrict__ Bh, const __nv_bfloat16* __restrict__ Bl,
                  const float* __restrict__ bias, float* __restrict__ C,
                  int M, int row0, int col0, char* smraw)
{
    const int tid  = threadIdx.x;
    const int lane = tid & 31;
    const int wid  = tid >> 5;
    const int warp_m = wid >> 2;       // 0..1
    const int warp_n = wid & 3;        // 0..3
    const uint32_t smb = smem_u32(smraw);

    // per-thread gmem/smem load mapping: 2 chunks of 8 bf16 per matrix
    const int ldrow = tid >> 1;             // 0..127
    const int ldc8  = (tid & 1) * 16;       // 0 or 16
    const bool okA  = (row0 + ldrow) < M;
    const size_t agoff = (size_t)(row0 + ldrow) * ND;
    const size_t bgoff = (size_t)(col0 + ldrow) * ND;
    const uint32_t srow = (uint32_t)ldrow * 40;
    const int szA = okA ? 16 : 0;

    float acc[4][4][4];
#pragma unroll
    for (int mi = 0; mi < 4; mi++)
#pragma unroll
        for (int ni = 0; ni < 4; ni++)
#pragma unroll
            for (int e = 0; e < 4; e++) acc[mi][ni][e] = 0.f;

    // ldmatrix per-thread base offsets (bf16 units)
    const int a_row = warp_m * 64 + (lane & 7) + ((lane >> 3) & 1) * 8;
    const int b_row = warp_n * 32 + (lane & 7) + ((lane >> 3) & 1) * 8;
    const int lm_k  = (lane >> 4) * 8;

    auto load_tile = [&](int k0, int buf) {
        uint32_t sb = smb + buf * MT_BUF;
#pragma unroll
        for (int c = 0; c < 2; c++) {
            int col = ldc8 + c * 8;
            uint32_t so = (srow + col) * 2;
            cpa16(sb + MT_AH + so, Ah + agoff + k0 + col, szA);
            cpa16(sb + MT_AL + so, Al + agoff + k0 + col, szA);
            cpa16(sb + MT_BH + so, Bh + bgoff + k0 + col, 16);
            cpa16(sb + MT_BL + so, Bl + bgoff + k0 + col, 16);
        }
    };

    load_tile(0, 0);
    cpa_commit();

    int buf = 0;
    for (int it = 0; it < 16; it++) {
        cpa_wait0();
        __syncthreads();
        if (it < 15) {
            load_tile((it + 1) * 32, buf ^ 1);
            cpa_commit();
        }
        const uint32_t sb = smb + buf * MT_BUF;
#pragma unroll
        for (int ks = 0; ks < 2; ks++) {
            const int kofs = ks * 16 + lm_k;
            uint32_t bh[2][4], bl[2][4];
#pragma unroll
            for (int p = 0; p < 2; p++) {
                uint32_t off = (uint32_t)((b_row + p * 16) * 40 + kofs) * 2;
                LDSM4(bh[p], sb + MT_BH + off);
                LDSM4(bl[p], sb + MT_BL + off);
            }
#pragma unroll
            for (int mi = 0; mi < 4; mi++) {
                uint32_t ah[4], al[4];
                uint32_t off = (uint32_t)((a_row + mi * 16) * 40 + kofs) * 2;
                LDSM4(ah, sb + MT_AH + off);
                LDSM4(al, sb + MT_AL + off);
#pragma unroll
                for (int ni = 0; ni < 4; ni++) {
                    const int p = ni >> 1, hi = ni & 1;
                    MMA16816(acc[mi][ni], ah, bh[p][hi], bh[p][hi + 2]);
                    MMA16816(acc[mi][ni], ah, bl[p][hi], bl[p][hi + 2]);
                    MMA16816(acc[mi][ni], al, bh[p][hi], bh[p][hi + 2]);
                }
            }
        }
        buf ^= 1;
    }

    // epilogue: thread owns rows (T/4, T/4+8), cols (T%4)*2,+1 per frag
#pragma unroll
    for (int mi = 0; mi < 4; mi++) {
        const int r0 = row0 + warp_m * 64 + mi * 16 + (lane >> 2);
#pragma unroll
        for (int ni = 0; ni < 4; ni++) {
            const int col = col0 + warp_n * 32 + ni * 8 + (lane & 3) * 2;
            const float b0 = bias ? bias[col] : 0.f;
            const float b1 = bias ? bias[col + 1] : 0.f;
#pragma unroll
            for (int half = 0; half < 2; half++) {
                const int m = r0 + half * 8;
                if (m >= M) continue;
                float2 o;
                o.x = acc[mi][ni][half * 2 + 0] + b0;
                o.y = acc[mi][ni][half * 2 + 1] + b1;
                if (MODE == 0) {
                    *(float2*)(C + (size_t)m * ND + col) = o;
                } else if (MODE == 1) {
                    int b = m >> 10, t = m & 1023;
                    int h = col >> 6, d = col & 63;
                    *(float2*)(C + ((size_t)((b << 3) + h) * NT + t) * NDH + d) = o;
                } else {
                    int h = col >> 6, d = col & 63;
                    *(float2*)(C + ((size_t)h * NSPOS + m) * NDH + d) = o;
                }
            }
        }
    }
}

template<int MODE>
__global__ __launch_bounds__(256, 2)
void mmagemm_k(const __nv_bfloat16* __restrict__ Ah, const __nv_bfloat16* __restrict__ Al,
               const __nv_bfloat16* __restrict__ Bh, const __nv_bfloat16* __restrict__ Bl,
               const float* __restrict__ bias, float* __restrict__ C, int M)
{
    extern __shared__ char smraw[];
    mmagemm_body<MODE>(Ah, Al, Bh, Bl, bias, C, M,
                       blockIdx.x << 7, blockIdx.y << 7, smraw);
}

// Fused QKV + pos projection: z = 0/1/2 -> Q/K/V (M=8192), z=3 -> pos (M=2047)
__global__ __launch_bounds__(256, 2)
void mmagemm_fused_k(const __nv_bfloat16* __restrict__ xh, const __nv_bfloat16* __restrict__ xl,
                     const __nv_bfloat16* __restrict__ peh, const __nv_bfloat16* __restrict__ pel,
                     const __nv_bfloat16* __restrict__ wth, const __nv_bfloat16* __restrict__ wtl,
                     const float* __restrict__ bq, const float* __restrict__ bk,
                     const float* __restrict__ bv,
                     float* __restrict__ Cq, float* __restrict__ Ck,
                     float* __restrict__ Cv, float* __restrict__ Cp)
{
    extern __shared__ char smraw[];
    const int z = blockIdx.z;
    const size_t WSZ = (size_t)ND * ND;
    if (z == 3) {
        if (blockIdx.x >= 16) return;
        mmagemm_body<2>(peh, pel, wth + 3 * WSZ, wtl + 3 * WSZ, nullptr, Cp, NSPOS,
                        blockIdx.x << 7, blockIdx.y << 7, smraw);
    } else {
        const float* bias = (z == 0) ? bq : (z == 1) ? bk : bv;
        float* C = (z == 0) ? Cq : (z == 1) ? Ck : Cv;
        mmagemm_body<1>(xh, xl, wth + z * WSZ, wtl + z * WSZ, bias, C, NB * NT,
                        blockIdx.x << 7, blockIdx.y << 7, smraw);
    }
}

// ---------------------------------------------------------------------------
// Precompute uk[b,h,s] = pos_bias_u[h] . k[b,h,s],  vp[h,i] = pos_bias_v[h] . p[h,i]
// ---------------------------------------------------------------------------
#define NUKROWS (NB*NH*NT)
#define NVPROWS (NH*NSPOS)
__global__ __launch_bounds__(256)
void biasdot_k(const float* __restrict__ k, const float* __restrict__ p,
               const float* __restrict__ pbu, const float* __restrict__ pbv,
               float* __restrict__ uk, float* __restrict__ vp)
{
    int w = (blockIdx.x * 256 + threadIdx.x) >> 5;
    int lane = threadIdx.x & 31;
    if (w < NUKROWS) {
        int h = (w >> 10) & 7;
        float2 a = *(const float2*)(k + (size_t)w * NDH + lane * 2);
        float2 u = *(const float2*)(pbu + h * NDH + lane * 2);
        float s = a.x * u.x + a.y * u.y;
#pragma unroll
        for (int off = 16; off >= 1; off >>= 1)
            s += __shfl_xor_sync(0xffffffffu, s, off);
        if (lane == 0) uk[w] = s;
    } else if (w < NUKROWS + NVPROWS) {
        int r = w - NUKROWS;
        float2 a = *(const float2*)(p + (size_t)r * NDH + lane * 2);
        int h = r / NSPOS;
        float2 u = *(const float2*)(pbv + h * NDH + lane * 2);
        float s = a.x * u.x + a.y * u.y;
#pragma unroll
        for (int off = 16; off >= 1; off >>= 1)
            s += __shfl_xor_sync(0xffffffffu, s, off);
        if (lane == 0) vp[r] = s;
    }
}

// ---------------------------------------------------------------------------
// Flash attention (unchanged from R9): 128q x 64k tiles, LDS.128 swizzled.
// ---------------------------------------------------------------------------
#define SQ_OFF 0
#define SK_OFF 8192
#define SP_OFF 12288
#define SV_OFF 24512
#define SPR_OFF 28864
#define SUK_OFF 45504
#define SVP_OFF 45568
#define SM_FLOATS 45760

__global__ __launch_bounds__(256)
void attn_k(const float* __restrict__ q, const float* __restrict__ k,
            const float* __restrict__ v, const float* __restrict__ p,
            const float* __restrict__ uk, const float* __restrict__ vp,
            float* __restrict__ out)
{
    extern __shared__ float sm[];
    float* sq  = sm + SQ_OFF;
    float* sk_ = sm + SK_OFF;
    float* sp_ = sm + SP_OFF;
    float* sv_ = sm + SV_OFF;
    float* sPs = sm + SPR_OFF;
    float* suk = sm + SUK_OFF;
    float* svp = sm + SVP_OFF;

    const int tid = threadIdx.x;
    const int tx = tid >> 4;
    const int ty = tid & 15;
    const int bx = blockIdx.x;
    const int t0 = (bx & 7) << 7;
    const int bh = bx >> 3;
    const int h  = bh & 7;
    const int b  = bh >> 3;

    const float* qb = q + ((size_t)bh * NT + t0) * NDH;
    const float* kb = k + (size_t)bh * NT * NDH;
    const float* vb = v + (size_t)bh * NT * NDH;
    const float* pb = p + (size_t)h * NSPOS * NDH;

#pragma unroll
    for (int pp = 0; pp < 8; pp++) {
        int e = tid + (pp << 8);
        int r = e >> 4;
        int c4 = e & 15;
        float4 t = *(const float4*)(qb + r * NDH + (c4 << 2));
        *(float4*)(sq + r * 64 + (((c4 ^ (r & 15)) << 2))) = t;
    }

    ull O2[8][2];
    float m_i[8], l_i[8];
#pragma unroll
    for (int i = 0; i < 8; i++) {
        m_i[i] = -3.0e38f;
        l_i[i] = 0.f;
        O2[i][0] = 0ull;
        O2[i][1] = 0ull;
    }

    const int pbrow = ty - tx + 15;
    const int pb15  = pbrow & 15;

    for (int s0 = 0; s0 < NT; s0 += 64) {
        __syncthreads();
#pragma unroll
        for (int pp = 0; pp < 4; pp++) {
            int e = tid + (pp << 8);
            int r = e >> 4;
            int c4 = e & 15;
            float4 kk = *(const float4*)(kb + (size_t)(s0 + r) * NDH + (c4 << 2));
            *(float4*)(sk_ + r * 64 + ((c4 ^ (r & 15)) << 2)) = kk;
            float4 vv = *(const float4*)(vb + (size_t)(s0 + r) * NDH + (c4 << 2));
            *(float4*)(sv_ + r * 68 + (c4 << 2)) = vv;
        }
        const int pbase = 896 + s0 - t0;
#pragma unroll
        for (int pp = 0; pp < 12; pp++) {
            int e = tid + (pp << 8);
            if (e < 191 * 16) {
                int r = e >> 4;
                int c4 = e & 15;
                float4 pv4 = *(const float4*)(pb + (size_t)(pbase + r) * NDH + (c4 << 2));
                *(float4*)(sp_ + r * 64 + ((c4 ^ (r & 15)) << 2)) = pv4;
            }
        }
        if (tid < 64)  suk[tid] = uk[bh * NT + s0 + tid];
        if (tid < 191) svp[tid] = vp[h * NSPOS + pbase + tid];
        __syncthreads();

        ull S2[8][4];
#pragma unroll
        for (int i = 0; i < 8; i++)
#pragma unroll
            for (int j = 0; j < 4; j++) S2[i][j] = 0ull;

#pragma unroll 2
        for (int c4 = 0; c4 < 16; c4++) {
            ulonglong2 qv[8], kv[4], pv[11];
            const int qoff = (c4 ^ tx) << 2;
            const int koff = (c4 ^ ty) << 2;
            const int poff = (c4 ^ pb15) << 2;
#pragma unroll
            for (int i = 0; i < 8; i++)
                qv[i] = *(const ulonglong2*)(sq + (tx + (i << 4)) * 64 + qoff);
#pragma unroll
            for (int j = 0; j < 4; j++)
                kv[j] = *(const ulonglong2*)(sk_ + (ty + (j << 4)) * 64 + koff);
#pragma unroll
            for (int dl = 0; dl < 11; dl++)
                pv[dl] = *(const ulonglong2*)(sp_ + (pbrow + (dl << 4)) * 64 + poff);
#pragma unroll
            for (int i = 0; i < 8; i++)
#pragma unroll
                for (int j = 0; j < 4; j++) {
                    ffma2(S2[i][j], qv[i].x, kv[j].x);
                    ffma2(S2[i][j], qv[i].y, kv[j].y);
                    ffma2(S2[i][j], qv[i].x, pv[j - i + 7].x);
                    ffma2(S2[i][j], qv[i].y, pv[j - i + 7].y);
                }
        }

#pragma unroll
        for (int i = 0; i < 8; i++) {
            float s[4];
            float mt = -3.0e38f;
#pragma unroll
            for (int j = 0; j < 4; j++) {
                float2 f = unpk(S2[i][j]);
                s[j] = (f.x + f.y + suk[ty + (j << 4)]
                        + svp[pbrow + ((j - i + 7) << 4)]) * ATT_SCALE;
                mt = fmaxf(mt, s[j]);
            }
#pragma unroll
            for (int off = 8; off >= 1; off >>= 1)
                mt = fmaxf(mt, __shfl_xor_sync(0xffffffffu, mt, off));
            float mn = fmaxf(m_i[i], mt);
            float alpha = __expf(m_i[i] - mn);
            m_i[i] = mn;
            float rs = 0.f;
#pragma unroll
            for (int j = 0; j < 4; j++) {
                float ev = __expf(s[j] - mn);
                s[j] = ev;
                rs += ev;
            }
#pragma unroll
            for (int off = 8; off >= 1; off >>= 1)
                rs += __shfl_xor_sync(0xffffffffu, rs, off);
            l_i[i] = l_i[i] * alpha + rs;
            ull ad = fdup(alpha);
            fmul2(O2[i][0], ad);
            fmul2(O2[i][1], ad);
#pragma unroll
            for (int j = 0; j < 4; j++)
                sPs[(tx + (i << 4)) * 130 + ty + (j << 4)] = s[j];
        }
        __syncthreads();

#pragma unroll 4
        for (int c = 0; c < 64; c++) {
            ulonglong2 vv = *(const ulonglong2*)(sv_ + c * 68 + (ty << 2));
#pragma unroll
            for (int i = 0; i < 8; i++) {
                ull pd = fdup(sPs[(tx + (i << 4)) * 130 + c]);
                ffma2(O2[i][0], pd, vv.x);
                ffma2(O2[i][1], pd, vv.y);
            }
        }
    }

#pragma unroll
    for (int i = 0; i < 8; i++) {
        float inv = 1.f / l_i[i];
        float2 a = unpk(O2[i][0]);
        float2 c2 = unpk(O2[i][1]);
        float4 o;
        o.x = a.x * inv;  o.y = a.y * inv;
        o.z = c2.x * inv; o.w = c2.y * inv;
        int r = tx + (i << 4);
        *(float4*)(out + ((size_t)b * NT + t0 + r) * ND + h * NDH + (ty << 2)) = o;
    }
}

// ---------------------------------------------------------------------------
extern "C" void kernel_launch(void* const* d_in, const int* in_sizes, int n_in,
                              void* d_out, int out_size)
{
    const float* x    = (const float*)d_in[0];
    const float* pe   = (const float*)d_in[1];
    const float* Wq   = (const float*)d_in[2];
    const float* bq   = (const float*)d_in[3];
    const float* Wk   = (const float*)d_in[4];
    const float* bk   = (const float*)d_in[5];
    const float* Wv   = (const float*)d_in[6];
    const float* bv   = (const float*)d_in[7];
    const float* Wpos = (const float*)d_in[8];
    const float* pbu  = (const float*)d_in[9];
    const float* pbv  = (const float*)d_in[10];
    const float* Wo   = (const float*)d_in[11];
    const float* bo   = (const float*)d_in[12];
    float* out = (float*)d_out;

    float *qp, *kp, *vp_, *pp, *aop, *ukp, *vpp;
    cudaGetSymbolAddress((void**)&qp,  g_q);
    cudaGetSymbolAddress((void**)&kp,  g_k);
    cudaGetSymbolAddress((void**)&vp_, g_v);
    cudaGetSymbolAddress((void**)&pp,  g_p);
    cudaGetSymbolAddress((void**)&aop, g_ao);
    cudaGetSymbolAddress((void**)&ukp, g_uk);
    cudaGetSymbolAddress((void**)&vpp, g_vp);
    __nv_bfloat16 *xh, *xl, *peh, *pel, *wth, *wtl, *aoh, *aol;
    cudaGetSymbolAddress((void**)&xh,  g_xh);
    cudaGetSymbolAddress((void**)&xl,  g_xl);
    cudaGetSymbolAddress((void**)&peh, g_peh);
    cudaGetSymbolAddress((void**)&pel, g_pel);
    cudaGetSymbolAddress((void**)&wth, g_wth);
    cudaGetSymbolAddress((void**)&wtl, g_wtl);
    cudaGetSymbolAddress((void**)&aoh, g_aoh);
    cudaGetSymbolAddress((void**)&aol, g_aol);

    cudaFuncSetAttribute(mmagemm_fused_k, cudaFuncAttributeMaxDynamicSharedMemorySize, MT_SMEM);
    cudaFuncSetAttribute(mmagemm_k<0>,    cudaFuncAttributeMaxDynamicSharedMemorySize, MT_SMEM);
    const int smem = SM_FLOATS * (int)sizeof(float);
    cudaFuncSetAttribute(attn_k, cudaFuncAttributeMaxDynamicSharedMemorySize, smem);

    const size_t WSZ = (size_t)ND * ND;
    dim3 blk(256);

    split_k<<<(NB*NT*ND/4 + 255)/256, blk>>>(x,  xh,  xl,  NB*NT*ND/4);
    split_k<<<(NSPOS*ND/4 + 255)/256, blk>>>(pe, peh, pel, NSPOS*ND/4);
    wsplit_k<<<dim3(16, 16, 5), blk>>>(Wq, Wk, Wv, Wpos, Wo, wth, wtl);

    mmagemm_fused_k<<<dim3(64, 4, 4), blk, MT_SMEM>>>(xh, xl, peh, pel, wth, wtl,
                                                      bq, bk, bv, qp, kp, vp_, pp);
    biasdot_k<<<(NUKROWS + NVPROWS + 7) / 8, blk>>>(kp, pp, pbu, pbv, ukp, vpp);
    attn_k<<<NB * NH * (NT / 128), blk, smem>>>(qp, kp, vp_, pp, ukp, vpp, aop);
    split_k<<<(NB*NT*ND/4 + 255)/256, blk>>>(aop, aoh, aol, NB*NT*ND/4);
    mmagemm_k<0><<<dim3(64, 4), blk, MT_SMEM>>>(aoh, aol, wth + 4*WSZ, wtl + 4*WSZ,
                                                bo, out, NB * NT);
}